// round 5
// baseline (speedup 1.0000x reference)
#include <cuda_runtime.h>
#include <math.h>
#include <float.h>

#define NN 50000
#define EE 600000
#define IN_F 128
#define EF_F 64
#define HH 4
#define OO 32
#define HO 128   // H*O

// ---------------- scratch (device globals: no allocation allowed) ----------------
__device__ float g_feat[NN * HO];          // GATv2 shared projection
__device__ float g_res [NN * HO];          // residual projection
__device__ float g_h   [NN * HO];          // relu(rst + res)
__device__ float g_ex  [EE * HH];          // exp(score) by CSR position
__device__ float g_m   [(size_t)EE * HO];  // messages m in CSR order
// CSR by dst (zero-init at module load; node_soft2 tail restores zeros each run)
__device__ int g_deg[NN];
__device__ int g_cur[NN];
__device__ int g_off[NN + 1];
__device__ int g_eid[EE];
__device__ int g_bsum[256];

// ---------------- CSR build ----------------
__global__ void count_kernel(const int* __restrict__ dst) {
    int e = blockIdx.x * blockDim.x + threadIdx.x;
    if (e < EE) atomicAdd(&g_deg[dst[e]], 1);
}

__global__ void scan1_kernel() {
    __shared__ int s[256];
    int t = threadIdx.x;
    int i = blockIdx.x * 256 + t;
    int v = (i < NN) ? g_deg[i] : 0;
    s[t] = v;
    __syncthreads();
#pragma unroll
    for (int o = 1; o < 256; o <<= 1) {
        int x = (t >= o) ? s[t - o] : 0;
        __syncthreads();
        s[t] += x;
        __syncthreads();
    }
    if (i < NN) g_off[i] = s[t] - v;          // exclusive within block
    if (t == 255) g_bsum[blockIdx.x] = s[255];
}

__global__ void scan2_kernel(int nblocks) {
    __shared__ int s[256];
    int t = threadIdx.x;
    int v = (t < nblocks) ? g_bsum[t] : 0;
    s[t] = v;
    __syncthreads();
#pragma unroll
    for (int o = 1; o < 256; o <<= 1) {
        int x = (t >= o) ? s[t - o] : 0;
        __syncthreads();
        s[t] += x;
        __syncthreads();
    }
    if (t < nblocks) g_bsum[t] = s[t] - v;    // exclusive block offsets
}

__global__ void scan3_kernel() {
    int i = blockIdx.x * 256 + threadIdx.x;
    if (i < NN) g_off[i] += g_bsum[blockIdx.x];
    if (i == 0) g_off[NN] = EE;
}

__global__ void scatter_kernel(const int* __restrict__ dst) {
    int e = blockIdx.x * blockDim.x + threadIdx.x;
    if (e < EE) {
        int d = dst[e];
        int p = atomicAdd(&g_cur[d], 1);
        g_eid[g_off[d] + p] = e;
    }
}

// ---------------- tf32 tensor-core GEMM, BK=64, dynamic smem ----------------
// BM=128, BN=128, 256 threads = 8 warps (2x4), 64x32 warp tile, m16n8k8 tf32.
__device__ __forceinline__ unsigned f2tf32(float f) {
    unsigned u;
    asm("cvt.rna.tf32.f32 %0, %1;" : "=r"(u) : "f"(f));
    return u;
}

__device__ __forceinline__ void mma_tf32(float* c, const unsigned* a, const unsigned* b) {
    asm volatile(
        "mma.sync.aligned.m16n8k8.row.col.f32.tf32.tf32.f32 "
        "{%0,%1,%2,%3}, {%4,%5,%6,%7}, {%8,%9}, {%0,%1,%2,%3};\n"
        : "+f"(c[0]), "+f"(c[1]), "+f"(c[2]), "+f"(c[3])
        : "r"(a[0]), "r"(a[1]), "r"(a[2]), "r"(a[3]), "r"(b[0]), "r"(b[1]));
}

#define SPAD 136
#define GEMM_SMEM_BYTES (2 * 64 * SPAD * 4)

// FUSE_EDGE=0: C[m][n] = A[m]@Wt + bias[n], rows are plain [0,M)
// FUSE_EDGE=1: rows are CSR positions; A row = edge_feats[eid[i]];
//              g_m[i][n] = acc + bias[n] + g_h[src[eid[i]]][n]
template <int FUSE_EDGE>
__global__ __launch_bounds__(256, 2) void mma_gemm(const float* __restrict__ A,
                                                   const float* __restrict__ Wt,
                                                   const float* __restrict__ bias,
                                                   const int* __restrict__ src,
                                                   float* __restrict__ C,
                                                   int M, int K) {
    extern __shared__ unsigned smem_u[];
    unsigned (*As)[SPAD] = (unsigned (*)[SPAD])smem_u;
    unsigned (*Bs)[SPAD] = (unsigned (*)[SPAD])(smem_u + 64 * SPAD);
    __shared__ int eid_s[128];

    int tid  = threadIdx.x;
    int lane = tid & 31;
    int wid  = tid >> 5;
    int g    = lane >> 2;
    int t    = lane & 3;
    int warp_m = (wid >> 2) * 64;
    int warp_n = (wid & 3) * 32;
    int bm = blockIdx.x * 128;

    if (FUSE_EDGE) {
        if (tid < 128) eid_s[tid] = (bm + tid < M) ? g_eid[bm + tid] : 0;
        __syncthreads();
    }

    float c[4][4][4];
#pragma unroll
    for (int mf = 0; mf < 4; mf++)
#pragma unroll
        for (int nf = 0; nf < 4; nf++)
#pragma unroll
            for (int r = 0; r < 4; r++) c[mf][nf][r] = 0.f;

    for (int k0 = 0; k0 < K; k0 += 64) {
        // load 128x64 A tile and 128x64 B tile; 8 float4 per thread per tile
#pragma unroll
        for (int r = 0; r < 8; r++) {
            int idx  = tid + 256 * r;        // 0..2047
            int row  = idx >> 4;             // 0..127
            int colq = (idx & 15) * 4;       // 0..60
            float4 av = make_float4(0.f, 0.f, 0.f, 0.f);
            if (bm + row < M) {
                const float* arow = FUSE_EDGE
                    ? &A[(size_t)eid_s[row] * K]
                    : &A[(size_t)(bm + row) * K];
                av = *(const float4*)&arow[k0 + colq];
            }
            As[colq + 0][row] = f2tf32(av.x); As[colq + 1][row] = f2tf32(av.y);
            As[colq + 2][row] = f2tf32(av.z); As[colq + 3][row] = f2tf32(av.w);
            float4 wv = *(const float4*)&Wt[(size_t)row * K + k0 + colq];
            Bs[colq + 0][row] = f2tf32(wv.x); Bs[colq + 1][row] = f2tf32(wv.y);
            Bs[colq + 2][row] = f2tf32(wv.z); Bs[colq + 3][row] = f2tf32(wv.w);
        }
        __syncthreads();

#pragma unroll
        for (int ks = 0; ks < 64; ks += 8) {
            unsigned a[4][4], b[4][2];
#pragma unroll
            for (int mf = 0; mf < 4; mf++) {
                int m0 = warp_m + mf * 16 + g;
                a[mf][0] = As[ks + t][m0];
                a[mf][1] = As[ks + t][m0 + 8];
                a[mf][2] = As[ks + t + 4][m0];
                a[mf][3] = As[ks + t + 4][m0 + 8];
            }
#pragma unroll
            for (int nf = 0; nf < 4; nf++) {
                int n0 = warp_n + nf * 8 + g;
                b[nf][0] = Bs[ks + t][n0];
                b[nf][1] = Bs[ks + t + 4][n0];
            }
#pragma unroll
            for (int mf = 0; mf < 4; mf++)
#pragma unroll
                for (int nf = 0; nf < 4; nf++)
                    mma_tf32(c[mf][nf], a[mf], b[nf]);
        }
        __syncthreads();
    }

    // epilogue: c0:(g, 2t) c1:(g, 2t+1) c2:(g+8, 2t) c3:(g+8, 2t+1)
#pragma unroll
    for (int mf = 0; mf < 4; mf++) {
        int r0 = bm + warp_m + mf * 16 + g;
        int r1 = r0 + 8;
        const float* h0 = nullptr;
        const float* h1 = nullptr;
        if (FUSE_EDGE) {
            if (r0 < M) h0 = &g_h[(size_t)src[eid_s[r0 - bm]] * HO];
            if (r1 < M) h1 = &g_h[(size_t)src[eid_s[r1 - bm]] * HO];
        }
#pragma unroll
        for (int nf = 0; nf < 4; nf++) {
            int col = warp_n + nf * 8 + t * 2;
            float2 bb = *(const float2*)&bias[col];
            if (r0 < M) {
                float2 v = make_float2(c[mf][nf][0] + bb.x, c[mf][nf][1] + bb.y);
                if (FUSE_EDGE) {
                    float2 hv = *(const float2*)&h0[col];
                    v.x += hv.x; v.y += hv.y;
                    *(float2*)&g_m[(size_t)r0 * HO + col] = v;
                } else {
                    *(float2*)&C[(size_t)r0 * HO + col] = v;
                }
            }
            if (r1 < M) {
                float2 v = make_float2(c[mf][nf][2] + bb.x, c[mf][nf][3] + bb.y);
                if (FUSE_EDGE) {
                    float2 hv = *(const float2*)&h1[col];
                    v.x += hv.x; v.y += hv.y;
                    *(float2*)&g_m[(size_t)r1 * HO + col] = v;
                } else {
                    *(float2*)&C[(size_t)r1 * HO + col] = v;
                }
            }
        }
    }
}

// ---------------- phase 1: fused GATv2 scores + softmax + aggregation + residual+relu
__global__ void node_attn_kernel(const int* __restrict__ src, const float* __restrict__ attn_v) {
    int gid = blockIdx.x * blockDim.x + threadIdx.x;
    int node = gid >> 5;
    int lane = gid & 31;
    if (node >= NN) return;
    int beg = g_off[node], end = g_off[node + 1];

    float fd[HH], av[HH];
#pragma unroll
    for (int h = 0; h < HH; h++) {
        fd[h] = g_feat[(size_t)node * HO + h * OO + lane];
        av[h] = __ldg(&attn_v[h * OO + lane]);
    }

    float den[HH] = {0.f, 0.f, 0.f, 0.f};
    for (int i = beg; i < end; i++) {
        int e = g_eid[i];
        int s = src[e];
        float sc[HH];
#pragma unroll
        for (int h = 0; h < HH; h++) {
            float v = g_feat[(size_t)s * HO + h * OO + lane] + fd[h];
            v = v > 0.f ? v : 0.2f * v;
            sc[h] = v * av[h];
        }
#pragma unroll
        for (int off = 16; off; off >>= 1)
#pragma unroll
            for (int h = 0; h < HH; h++) sc[h] += __shfl_xor_sync(0xffffffffu, sc[h], off);
        float ex[HH];
#pragma unroll
        for (int h = 0; h < HH; h++) { ex[h] = __expf(sc[h]); den[h] += ex[h]; }
        if (lane < HH) g_ex[(size_t)i * HH + lane] = ex[lane];
    }
    float inv[HH];
#pragma unroll
    for (int h = 0; h < HH; h++) inv[h] = den[h] > 0.f ? 1.f / den[h] : 0.f;

    float acc[HH] = {0.f, 0.f, 0.f, 0.f};
    for (int i = beg; i < end; i++) {
        int e = g_eid[i];
        int s = src[e];
        const float* frow = &g_feat[(size_t)s * HO];
#pragma unroll
        for (int h = 0; h < HH; h++) {
            float al = g_ex[(size_t)i * HH + h] * inv[h];
            acc[h] += al * frow[h * OO + lane];
        }
    }
#pragma unroll
    for (int h = 0; h < HH; h++) {
        int c = h * OO + lane;
        float v = acc[h] + g_res[(size_t)node * HO + c];
        g_h[(size_t)node * HO + c] = v > 0.f ? v : 0.f;
    }
}

// ---------------- phase 2: streaming softmax-weighted mean over CSR-ordered m ------
__global__ void node_soft2_kernel(float* __restrict__ out) {
    int gid = blockIdx.x * blockDim.x + threadIdx.x;
    int node = gid >> 5;
    int lane = gid & 31;
    if (node >= NN) return;
    int beg = g_off[node], end = g_off[node + 1];

    float dn[4] = {0.f, 0.f, 0.f, 0.f};
    float nm[4] = {0.f, 0.f, 0.f, 0.f};
    for (int i = beg; i < end; i++) {
        const float* mrow = &g_m[(size_t)i * HO];   // contiguous per node
#pragma unroll
        for (int j = 0; j < 4; j++) {
            float m = mrow[j * 32 + lane];
            float ex = __expf(m);
            dn[j] += ex;
            nm[j] += ex * m;
        }
    }
#pragma unroll
    for (int j = 0; j < 4; j++) {
        out[(size_t)node * HO + j * 32 + lane] = dn[j] > 0.f ? nm[j] / dn[j] : 0.f;
    }
    // restore CSR-counter invariant for the next graph replay
    if (lane == 0) { g_deg[node] = 0; g_cur[node] = 0; }
}

// ---------------- launch ----------------
extern "C" void kernel_launch(void* const* d_in, const int* in_sizes, int n_in,
                              void* d_out, int out_size) {
    const float* node_feats = (const float*)d_in[0];
    const float* edge_feats = (const float*)d_in[1];
    const int*   src        = (const int*)  d_in[2];
    const int*   dst        = (const int*)  d_in[3];
    const float* W          = (const float*)d_in[4];
    const float* b          = (const float*)d_in[5];
    const float* attn_v     = (const float*)d_in[6];
    const float* Wres       = (const float*)d_in[7];
    const float* bres       = (const float*)d_in[8];
    const float* We         = (const float*)d_in[9];
    const float* be         = (const float*)d_in[10];
    float* out = (float*)d_out;

    void *p_feat, *p_res;
    cudaGetSymbolAddress(&p_feat, g_feat);
    cudaGetSymbolAddress(&p_res,  g_res);

    cudaFuncSetAttribute(mma_gemm<0>, cudaFuncAttributeMaxDynamicSharedMemorySize, GEMM_SMEM_BYTES);
    cudaFuncSetAttribute(mma_gemm<1>, cudaFuncAttributeMaxDynamicSharedMemorySize, GEMM_SMEM_BYTES);

    const int NB_NODE = (NN + 127) / 128;   // 391
    const int NB_EDGE = (EE + 127) / 128;   // 4688
    const int SCAN_BLOCKS = (NN + 255) / 256;   // 196

    count_kernel<<<(EE + 255) / 256, 256>>>(dst);                            // 0
    scan1_kernel<<<SCAN_BLOCKS, 256>>>();                                    // 1
    scan2_kernel<<<1, 256>>>(SCAN_BLOCKS);                                   // 2
    mma_gemm<0><<<NB_NODE, 256, GEMM_SMEM_BYTES>>>(node_feats, W, b, nullptr,
                                                   (float*)p_feat, NN, IN_F);// 3 (profiled)
    mma_gemm<0><<<NB_NODE, 256, GEMM_SMEM_BYTES>>>(node_feats, Wres, bres, nullptr,
                                                   (float*)p_res, NN, IN_F); // 4
    scan3_kernel<<<SCAN_BLOCKS, 256>>>();                                    // 5
    scatter_kernel<<<(EE + 255) / 256, 256>>>(dst);                          // 6
    node_attn_kernel<<<(NN * 32 + 255) / 256, 256>>>(src, attn_v);           // 7
    mma_gemm<1><<<NB_EDGE, 256, GEMM_SMEM_BYTES>>>(edge_feats, We, be, src,
                                                   nullptr, EE, EF_F);       // 8
    node_soft2_kernel<<<(NN * 32 + 255) / 256, 256>>>(out);                  // 9
}

// round 6
// speedup vs baseline: 1.2250x; 1.2250x over previous
#include <cuda_runtime.h>
#include <math.h>
#include <float.h>

#define NN 50000
#define EE 600000
#define IN_F 128
#define EF_F 64
#define HH 4
#define OO 32
#define HO 128   // H*O

// ---------------- scratch (device globals: no allocation allowed) ----------------
__device__ float g_feat[NN * HO];          // GATv2 shared projection
__device__ float g_res [NN * HO];          // residual projection
__device__ float g_h   [NN * HO];          // relu(rst + res)
__device__ float g_ex  [EE * HH];          // exp(score) by CSR position
__device__ float g_m   [(size_t)EE * HO];  // messages m in CSR order
// CSR by dst (zero-init at module load; node_soft2 tail restores zeros each run)
__device__ int g_deg[NN];
__device__ int g_cur[NN];
__device__ int g_off[NN + 1];
__device__ int g_eid[EE];                  // CSR position -> edge id
__device__ int g_srcs[EE];                 // CSR position -> src node (pre-gathered)
__device__ int g_bsum[256];

// ---------------- CSR build ----------------
__global__ void count_kernel(const int* __restrict__ dst) {
    int e = blockIdx.x * blockDim.x + threadIdx.x;
    if (e < EE) atomicAdd(&g_deg[dst[e]], 1);
}

__global__ void scan1_kernel() {
    __shared__ int s[256];
    int t = threadIdx.x;
    int i = blockIdx.x * 256 + t;
    int v = (i < NN) ? g_deg[i] : 0;
    s[t] = v;
    __syncthreads();
#pragma unroll
    for (int o = 1; o < 256; o <<= 1) {
        int x = (t >= o) ? s[t - o] : 0;
        __syncthreads();
        s[t] += x;
        __syncthreads();
    }
    if (i < NN) g_off[i] = s[t] - v;          // exclusive within block
    if (t == 255) g_bsum[blockIdx.x] = s[255];
}

__global__ void scan2_kernel(int nblocks) {
    __shared__ int s[256];
    int t = threadIdx.x;
    int v = (t < nblocks) ? g_bsum[t] : 0;
    s[t] = v;
    __syncthreads();
#pragma unroll
    for (int o = 1; o < 256; o <<= 1) {
        int x = (t >= o) ? s[t - o] : 0;
        __syncthreads();
        s[t] += x;
        __syncthreads();
    }
    if (t < nblocks) g_bsum[t] = s[t] - v;    // exclusive block offsets
}

__global__ void scan3_kernel() {
    int i = blockIdx.x * 256 + threadIdx.x;
    if (i < NN) g_off[i] += g_bsum[blockIdx.x];
    if (i == 0) g_off[NN] = EE;
}

__global__ void scatter_kernel(const int* __restrict__ dst, const int* __restrict__ src) {
    int e = blockIdx.x * blockDim.x + threadIdx.x;
    if (e < EE) {
        int d = dst[e];
        int p = atomicAdd(&g_cur[d], 1);
        int i = g_off[d] + p;
        g_eid[i]  = e;
        g_srcs[i] = src[e];
    }
}

// ---------------- tf32 tensor-core GEMM (R4 config: BK=16, static smem) ----------
// BM=128, BN=128, BK=16, 256 threads = 8 warps (2x4), 64x32 warp tile, m16n8k8.
__device__ __forceinline__ unsigned f2tf32(float f) {
    unsigned u;
    asm("cvt.rna.tf32.f32 %0, %1;" : "=r"(u) : "f"(f));
    return u;
}

__device__ __forceinline__ void mma_tf32(float* c, const unsigned* a, const unsigned* b) {
    asm volatile(
        "mma.sync.aligned.m16n8k8.row.col.f32.tf32.tf32.f32 "
        "{%0,%1,%2,%3}, {%4,%5,%6,%7}, {%8,%9}, {%0,%1,%2,%3};\n"
        : "+f"(c[0]), "+f"(c[1]), "+f"(c[2]), "+f"(c[3])
        : "r"(a[0]), "r"(a[1]), "r"(a[2]), "r"(a[3]), "r"(b[0]), "r"(b[1]));
}

#define SPAD 136

// FUSE_EDGE=0: C[m][n] = A[m]@Wt + bias[n], rows are plain [0,M)
// FUSE_EDGE=1: rows are CSR positions; A row = edge_feats[g_eid[i]];
//              g_m[i][n] = acc + bias[n] + g_h[g_srcs[i]][n]
template <int FUSE_EDGE>
__global__ __launch_bounds__(256) void mma_gemm(const float* __restrict__ A,
                                                const float* __restrict__ Wt,
                                                const float* __restrict__ bias,
                                                float* __restrict__ C,
                                                int M, int K) {
    __shared__ unsigned As[16][SPAD];
    __shared__ unsigned Bs[16][SPAD];
    __shared__ int eid_s[128];

    int tid  = threadIdx.x;
    int lane = tid & 31;
    int wid  = tid >> 5;
    int g    = lane >> 2;     // 0..7
    int t    = lane & 3;      // 0..3
    int warp_m = (wid >> 2) * 64;   // 0 | 64
    int warp_n = (wid & 3) * 32;    // 0..96
    int bm = blockIdx.x * 128;

    if (FUSE_EDGE) {
        if (tid < 128) eid_s[tid] = (bm + tid < M) ? g_eid[bm + tid] : 0;
        __syncthreads();
    }

    float c[4][4][4];
#pragma unroll
    for (int mf = 0; mf < 4; mf++)
#pragma unroll
        for (int nf = 0; nf < 4; nf++)
#pragma unroll
            for (int r = 0; r < 4; r++) c[mf][nf][r] = 0.f;

    for (int k0 = 0; k0 < K; k0 += 16) {
#pragma unroll
        for (int r = 0; r < 2; r++) {
            int id  = tid + 256 * r;      // 0..511
            int row = id >> 2;            // 0..127
            int cq  = (id & 3) * 4;       // 0,4,8,12
            float4 av = make_float4(0.f, 0.f, 0.f, 0.f);
            if (bm + row < M) {
                const float* arow = FUSE_EDGE
                    ? &A[(size_t)eid_s[row] * K]
                    : &A[(size_t)(bm + row) * K];
                av = *(const float4*)&arow[k0 + cq];
            }
            As[cq + 0][row] = f2tf32(av.x); As[cq + 1][row] = f2tf32(av.y);
            As[cq + 2][row] = f2tf32(av.z); As[cq + 3][row] = f2tf32(av.w);
            float4 wv = *(const float4*)&Wt[(size_t)row * K + k0 + cq];
            Bs[cq + 0][row] = f2tf32(wv.x); Bs[cq + 1][row] = f2tf32(wv.y);
            Bs[cq + 2][row] = f2tf32(wv.z); Bs[cq + 3][row] = f2tf32(wv.w);
        }
        __syncthreads();

#pragma unroll
        for (int ks = 0; ks < 16; ks += 8) {
            unsigned a[4][4], b[4][2];
#pragma unroll
            for (int mf = 0; mf < 4; mf++) {
                int m0 = warp_m + mf * 16 + g;
                a[mf][0] = As[ks + t][m0];
                a[mf][1] = As[ks + t][m0 + 8];
                a[mf][2] = As[ks + t + 4][m0];
                a[mf][3] = As[ks + t + 4][m0 + 8];
            }
#pragma unroll
            for (int nf = 0; nf < 4; nf++) {
                int n0 = warp_n + nf * 8 + g;
                b[nf][0] = Bs[ks + t][n0];
                b[nf][1] = Bs[ks + t + 4][n0];
            }
#pragma unroll
            for (int mf = 0; mf < 4; mf++)
#pragma unroll
                for (int nf = 0; nf < 4; nf++)
                    mma_tf32(c[mf][nf], a[mf], b[nf]);
        }
        __syncthreads();
    }

    // epilogue: c0:(g, 2t) c1:(g, 2t+1) c2:(g+8, 2t) c3:(g+8, 2t+1)
#pragma unroll
    for (int mf = 0; mf < 4; mf++) {
        int r0 = bm + warp_m + mf * 16 + g;
        int r1 = r0 + 8;
        const float* h0 = nullptr;
        const float* h1 = nullptr;
        if (FUSE_EDGE) {
            if (r0 < M) h0 = &g_h[(size_t)g_srcs[r0] * HO];
            if (r1 < M) h1 = &g_h[(size_t)g_srcs[r1] * HO];
        }
#pragma unroll
        for (int nf = 0; nf < 4; nf++) {
            int col = warp_n + nf * 8 + t * 2;
            float2 bb = *(const float2*)&bias[col];
            if (r0 < M) {
                float2 v = make_float2(c[mf][nf][0] + bb.x, c[mf][nf][1] + bb.y);
                if (FUSE_EDGE) {
                    float2 hv = *(const float2*)&h0[col];
                    v.x += hv.x; v.y += hv.y;
                    *(float2*)&g_m[(size_t)r0 * HO + col] = v;
                } else {
                    *(float2*)&C[(size_t)r0 * HO + col] = v;
                }
            }
            if (r1 < M) {
                float2 v = make_float2(c[mf][nf][2] + bb.x, c[mf][nf][3] + bb.y);
                if (FUSE_EDGE) {
                    float2 hv = *(const float2*)&h1[col];
                    v.x += hv.x; v.y += hv.y;
                    *(float2*)&g_m[(size_t)r1 * HO + col] = v;
                } else {
                    *(float2*)&C[(size_t)r1 * HO + col] = v;
                }
            }
        }
    }
}

// ---------------- phase 1: fused GATv2 scores + softmax + aggregation + residual+relu
// warp per node; src ids pre-gathered in CSR order (g_srcs).
__global__ void node_attn_kernel(const float* __restrict__ attn_v) {
    int gid = blockIdx.x * blockDim.x + threadIdx.x;
    int node = gid >> 5;
    int lane = gid & 31;
    if (node >= NN) return;
    int beg = g_off[node], end = g_off[node + 1];

    float fd[HH], av[HH];
#pragma unroll
    for (int h = 0; h < HH; h++) {
        fd[h] = g_feat[(size_t)node * HO + h * OO + lane];
        av[h] = __ldg(&attn_v[h * OO + lane]);
    }

    float den[HH] = {0.f, 0.f, 0.f, 0.f};
    for (int i = beg; i < end; i++) {
        int s = g_srcs[i];
        float sc[HH];
#pragma unroll
        for (int h = 0; h < HH; h++) {
            float v = g_feat[(size_t)s * HO + h * OO + lane] + fd[h];
            v = v > 0.f ? v : 0.2f * v;
            sc[h] = v * av[h];
        }
#pragma unroll
        for (int off = 16; off; off >>= 1)
#pragma unroll
            for (int h = 0; h < HH; h++) sc[h] += __shfl_xor_sync(0xffffffffu, sc[h], off);
        float ex[HH];
#pragma unroll
        for (int h = 0; h < HH; h++) { ex[h] = __expf(sc[h]); den[h] += ex[h]; }
        if (lane < HH) g_ex[(size_t)i * HH + lane] = ex[lane];
    }
    float inv[HH];
#pragma unroll
    for (int h = 0; h < HH; h++) inv[h] = den[h] > 0.f ? 1.f / den[h] : 0.f;

    float acc[HH] = {0.f, 0.f, 0.f, 0.f};
    for (int i = beg; i < end; i++) {
        int s = g_srcs[i];
        const float* frow = &g_feat[(size_t)s * HO];
#pragma unroll
        for (int h = 0; h < HH; h++) {
            float al = g_ex[(size_t)i * HH + h] * inv[h];
            acc[h] += al * frow[h * OO + lane];
        }
    }
#pragma unroll
    for (int h = 0; h < HH; h++) {
        int c = h * OO + lane;
        float v = acc[h] + g_res[(size_t)node * HO + c];
        g_h[(size_t)node * HO + c] = v > 0.f ? v : 0.f;
    }
}

// ---------------- phase 2: streaming softmax-weighted mean over CSR-ordered m ------
__global__ void node_soft2_kernel(float* __restrict__ out) {
    int gid = blockIdx.x * blockDim.x + threadIdx.x;
    int node = gid >> 5;
    int lane = gid & 31;
    if (node >= NN) return;
    int beg = g_off[node], end = g_off[node + 1];

    float dn[4] = {0.f, 0.f, 0.f, 0.f};
    float nm[4] = {0.f, 0.f, 0.f, 0.f};
    for (int i = beg; i < end; i++) {
        const float* mrow = &g_m[(size_t)i * HO];   // contiguous per node
#pragma unroll
        for (int j = 0; j < 4; j++) {
            float m = mrow[j * 32 + lane];
            float ex = __expf(m);
            dn[j] += ex;
            nm[j] += ex * m;
        }
    }
#pragma unroll
    for (int j = 0; j < 4; j++) {
        out[(size_t)node * HO + j * 32 + lane] = dn[j] > 0.f ? nm[j] / dn[j] : 0.f;
    }
    // restore CSR-counter invariant for the next graph replay
    if (lane == 0) { g_deg[node] = 0; g_cur[node] = 0; }
}

// ---------------- launch ----------------
extern "C" void kernel_launch(void* const* d_in, const int* in_sizes, int n_in,
                              void* d_out, int out_size) {
    const float* node_feats = (const float*)d_in[0];
    const float* edge_feats = (const float*)d_in[1];
    const int*   src        = (const int*)  d_in[2];
    const int*   dst        = (const int*)  d_in[3];
    const float* W          = (const float*)d_in[4];
    const float* b          = (const float*)d_in[5];
    const float* attn_v     = (const float*)d_in[6];
    const float* Wres       = (const float*)d_in[7];
    const float* bres       = (const float*)d_in[8];
    const float* We         = (const float*)d_in[9];
    const float* be         = (const float*)d_in[10];
    float* out = (float*)d_out;

    void *p_feat, *p_res;
    cudaGetSymbolAddress(&p_feat, g_feat);
    cudaGetSymbolAddress(&p_res,  g_res);

    const int NB_NODE = (NN + 127) / 128;       // 391
    const int NB_EDGE = (EE + 127) / 128;       // 4688
    const int SCAN_BLOCKS = (NN + 255) / 256;   // 196

    count_kernel<<<(EE + 255) / 256, 256>>>(dst);                            // 0
    scan1_kernel<<<SCAN_BLOCKS, 256>>>();                                    // 1
    scan2_kernel<<<1, 256>>>(SCAN_BLOCKS);                                   // 2
    mma_gemm<0><<<NB_NODE, 256>>>(node_feats, W, b, (float*)p_feat, NN, IN_F);   // 3 (profiled)
    mma_gemm<0><<<NB_NODE, 256>>>(node_feats, Wres, bres, (float*)p_res, NN, IN_F); // 4
    scan3_kernel<<<SCAN_BLOCKS, 256>>>();                                    // 5
    scatter_kernel<<<(EE + 255) / 256, 256>>>(dst, src);                     // 6
    node_attn_kernel<<<(NN * 32 + 255) / 256, 256>>>(attn_v);                // 7
    mma_gemm<1><<<NB_EDGE, 256>>>(edge_feats, We, be, nullptr, EE, EF_F);    // 8
    node_soft2_kernel<<<(NN * 32 + 255) / 256, 256>>>(out);                  // 9
}

// round 7
// speedup vs baseline: 1.3874x; 1.1326x over previous
#include <cuda_runtime.h>
#include <math.h>
#include <float.h>

#define NN 50000
#define EE 600000
#define IN_F 128
#define EF_F 64
#define HH 4
#define OO 32
#define HO 128   // H*O

// ---------------- scratch (device globals: no allocation allowed) ----------------
__device__ float g_feat[NN * HO];          // GATv2 shared projection
__device__ float g_res [NN * HO];          // residual projection
__device__ float g_h   [NN * HO];          // relu(rst + res)
__device__ float g_dn  [NN * HO];          // phase-2 sum exp(m)      (reset by final)
__device__ float g_nm  [NN * HO];          // phase-2 sum m*exp(m)    (reset by final)
// CSR by dst (zero-init at module load; final_kernel restores zeros each run)
__device__ int g_deg[NN];
__device__ int g_cur[NN];
__device__ int g_off[NN + 1];
__device__ int g_eid [EE];                 // CSR position -> edge id
__device__ int g_srcs[EE];                 // CSR position -> src node
__device__ int g_dstc[EE];                 // CSR position -> dst node
__device__ int g_bsum[256];

// ---------------- CSR build ----------------
__global__ void count_kernel(const int* __restrict__ dst) {
    int e = blockIdx.x * blockDim.x + threadIdx.x;
    if (e < EE) atomicAdd(&g_deg[dst[e]], 1);
}

__global__ void scan1_kernel() {
    __shared__ int s[256];
    int t = threadIdx.x;
    int i = blockIdx.x * 256 + t;
    int v = (i < NN) ? g_deg[i] : 0;
    s[t] = v;
    __syncthreads();
#pragma unroll
    for (int o = 1; o < 256; o <<= 1) {
        int x = (t >= o) ? s[t - o] : 0;
        __syncthreads();
        s[t] += x;
        __syncthreads();
    }
    if (i < NN) g_off[i] = s[t] - v;
    if (t == 255) g_bsum[blockIdx.x] = s[255];
}

__global__ void scan2_kernel(int nblocks) {
    __shared__ int s[256];
    int t = threadIdx.x;
    int v = (t < nblocks) ? g_bsum[t] : 0;
    s[t] = v;
    __syncthreads();
#pragma unroll
    for (int o = 1; o < 256; o <<= 1) {
        int x = (t >= o) ? s[t - o] : 0;
        __syncthreads();
        s[t] += x;
        __syncthreads();
    }
    if (t < nblocks) g_bsum[t] = s[t] - v;
}

__global__ void scan3_kernel() {
    int i = blockIdx.x * 256 + threadIdx.x;
    if (i < NN) g_off[i] += g_bsum[blockIdx.x];
    if (i == 0) g_off[NN] = EE;
}

__global__ void scatter_kernel(const int* __restrict__ dst, const int* __restrict__ src) {
    int e = blockIdx.x * blockDim.x + threadIdx.x;
    if (e < EE) {
        int d = dst[e];
        int p = atomicAdd(&g_cur[d], 1);
        int i = g_off[d] + p;
        g_eid[i]  = e;
        g_srcs[i] = src[e];
        g_dstc[i] = d;
    }
}

// ---------------- tf32 tensor-core GEMM (BK=16, 128x128 tile, 8 warps) ----------
__device__ __forceinline__ unsigned f2tf32(float f) {
    unsigned u;
    asm("cvt.rna.tf32.f32 %0, %1;" : "=r"(u) : "f"(f));
    return u;
}

__device__ __forceinline__ void mma_tf32(float* c, const unsigned* a, const unsigned* b) {
    asm volatile(
        "mma.sync.aligned.m16n8k8.row.col.f32.tf32.tf32.f32 "
        "{%0,%1,%2,%3}, {%4,%5,%6,%7}, {%8,%9}, {%0,%1,%2,%3};\n"
        : "+f"(c[0]), "+f"(c[1]), "+f"(c[2]), "+f"(c[3])
        : "r"(a[0]), "r"(a[1]), "r"(a[2]), "r"(a[3]), "r"(b[0]), "r"(b[1]));
}

#define SPAD 136
#define AS_BYTES (16 * SPAD * 4)            // 8704
#define STG_BYTES (128 * 33 * 4)            // 16896
#define SMEM_RAW_BYTES (2 * STG_BYTES)      // 33792 >= 2*AS_BYTES

// FUSE_EDGE=0: C[m][n] = A[m]@Wt + bias[n], rows plain [0,M)
// FUSE_EDGE=1: rows are CSR positions; A row = edge_feats[g_eid[i]];
//   m = acc + bias + g_h[g_srcs[i]]; accumulate exp(m), m*exp(m) into
//   g_dn/g_nm per (dst node, channel) via smem staging + segmented atomics.
template <int FUSE_EDGE>
__global__ __launch_bounds__(256) void mma_gemm(const float* __restrict__ A,
                                                const float* __restrict__ Wt,
                                                const float* __restrict__ bias,
                                                float* __restrict__ C,
                                                int M, int K) {
    __shared__ __align__(16) unsigned char s_raw[SMEM_RAW_BYTES];
    unsigned (*As)[SPAD] = reinterpret_cast<unsigned (*)[SPAD]>(s_raw);
    unsigned (*Bs)[SPAD] = reinterpret_cast<unsigned (*)[SPAD]>(s_raw + AS_BYTES);
    float (*stg_ex)[33]  = reinterpret_cast<float (*)[33]>(s_raw);
    float (*stg_exm)[33] = reinterpret_cast<float (*)[33]>(s_raw + STG_BYTES);
    __shared__ int eid_s[128];
    __shared__ int node_s[128];

    int tid  = threadIdx.x;
    int lane = tid & 31;
    int wid  = tid >> 5;
    int g    = lane >> 2;     // 0..7
    int t    = lane & 3;      // 0..3
    int warp_m = (wid >> 2) * 64;   // 0 | 64
    int warp_n = (wid & 3) * 32;    // 0..96
    int bm = blockIdx.x * 128;

    if (FUSE_EDGE) {
        if (tid < 128) {
            int ok = (bm + tid < M);
            eid_s[tid]  = ok ? g_eid[bm + tid] : 0;
            node_s[tid] = ok ? g_dstc[bm + tid] : -1;
        }
        __syncthreads();
    }

    float c[4][4][4];
#pragma unroll
    for (int mf = 0; mf < 4; mf++)
#pragma unroll
        for (int nf = 0; nf < 4; nf++)
#pragma unroll
            for (int r = 0; r < 4; r++) c[mf][nf][r] = 0.f;

    for (int k0 = 0; k0 < K; k0 += 16) {
#pragma unroll
        for (int r = 0; r < 2; r++) {
            int id  = tid + 256 * r;
            int row = id >> 2;
            int cq  = (id & 3) * 4;
            float4 av = make_float4(0.f, 0.f, 0.f, 0.f);
            if (bm + row < M) {
                const float* arow = FUSE_EDGE
                    ? &A[(size_t)eid_s[row] * K]
                    : &A[(size_t)(bm + row) * K];
                av = *(const float4*)&arow[k0 + cq];
            }
            As[cq + 0][row] = f2tf32(av.x); As[cq + 1][row] = f2tf32(av.y);
            As[cq + 2][row] = f2tf32(av.z); As[cq + 3][row] = f2tf32(av.w);
            float4 wv = *(const float4*)&Wt[(size_t)row * K + k0 + cq];
            Bs[cq + 0][row] = f2tf32(wv.x); Bs[cq + 1][row] = f2tf32(wv.y);
            Bs[cq + 2][row] = f2tf32(wv.z); Bs[cq + 3][row] = f2tf32(wv.w);
        }
        __syncthreads();

#pragma unroll
        for (int ks = 0; ks < 16; ks += 8) {
            unsigned a[4][4], b[4][2];
#pragma unroll
            for (int mf = 0; mf < 4; mf++) {
                int m0 = warp_m + mf * 16 + g;
                a[mf][0] = As[ks + t][m0];
                a[mf][1] = As[ks + t][m0 + 8];
                a[mf][2] = As[ks + t + 4][m0];
                a[mf][3] = As[ks + t + 4][m0 + 8];
            }
#pragma unroll
            for (int nf = 0; nf < 4; nf++) {
                int n0 = warp_n + nf * 8 + g;
                b[nf][0] = Bs[ks + t][n0];
                b[nf][1] = Bs[ks + t + 4][n0];
            }
#pragma unroll
            for (int mf = 0; mf < 4; mf++)
#pragma unroll
                for (int nf = 0; nf < 4; nf++)
                    mma_tf32(c[mf][nf], a[mf], b[nf]);
        }
        __syncthreads();   // also separates Bs use from stg reuse below
    }

    if (!FUSE_EDGE) {
        // plain epilogue: C = acc + bias
#pragma unroll
        for (int mf = 0; mf < 4; mf++) {
            int r0 = bm + warp_m + mf * 16 + g;
            int r1 = r0 + 8;
#pragma unroll
            for (int nf = 0; nf < 4; nf++) {
                int col = warp_n + nf * 8 + t * 2;
                float2 bb = *(const float2*)&bias[col];
                if (r0 < M) {
                    float2 v = make_float2(c[mf][nf][0] + bb.x, c[mf][nf][1] + bb.y);
                    *(float2*)&C[(size_t)r0 * HO + col] = v;
                }
                if (r1 < M) {
                    float2 v = make_float2(c[mf][nf][2] + bb.x, c[mf][nf][3] + bb.y);
                    *(float2*)&C[(size_t)r1 * HO + col] = v;
                }
            }
        }
        return;
    }

    // ---- fused phase-2 reduction epilogue ----
    // local row lr in [0,32): lr = (wid>>2)*16 + g (+8); global row128 for walker:
    //   row128(lr, mf) = (lr>>4)*64 + mf*16 + (lr&15)
    int lr0 = (wid >> 2) * 16 + g;
    int lr1 = lr0 + 8;
    int col_w = tid & 127;        // walker column
    int sel   = tid >> 7;         // 0: ex->g_dn, 1: exm->g_nm

#pragma unroll
    for (int mf = 0; mf < 4; mf++) {
        int r0 = bm + warp_m + mf * 16 + g;
        int r1 = r0 + 8;
        const float* h0 = (r0 < M) ? &g_h[(size_t)g_srcs[r0] * HO] : nullptr;
        const float* h1 = (r1 < M) ? &g_h[(size_t)g_srcs[r1] * HO] : nullptr;
#pragma unroll
        for (int nf = 0; nf < 4; nf++) {
            int col = warp_n + nf * 8 + t * 2;
            float2 bb = *(const float2*)&bias[col];
            float ex0x = 0.f, ex0y = 0.f, em0x = 0.f, em0y = 0.f;
            float ex1x = 0.f, ex1y = 0.f, em1x = 0.f, em1y = 0.f;
            if (r0 < M) {
                float2 hv = *(const float2*)&h0[col];
                float mx = c[mf][nf][0] + bb.x + hv.x;
                float my = c[mf][nf][1] + bb.y + hv.y;
                ex0x = __expf(mx); em0x = ex0x * mx;
                ex0y = __expf(my); em0y = ex0y * my;
            }
            if (r1 < M) {
                float2 hv = *(const float2*)&h1[col];
                float mx = c[mf][nf][2] + bb.x + hv.x;
                float my = c[mf][nf][3] + bb.y + hv.y;
                ex1x = __expf(mx); em1x = ex1x * mx;
                ex1y = __expf(my); em1y = ex1y * my;
            }
            stg_ex [col][lr0]     = ex0x;  stg_ex [col + 1][lr0] = ex0y;
            stg_exm[col][lr0]     = em0x;  stg_exm[col + 1][lr0] = em0y;
            stg_ex [col][lr1]     = ex1x;  stg_ex [col + 1][lr1] = ex1y;
            stg_exm[col][lr1]     = em1x;  stg_exm[col + 1][lr1] = em1y;
        }
        __syncthreads();

        // walkers: 2 runs of 16 consecutive CSR positions each
        const float (*arr)[33] = sel ? stg_exm : stg_ex;
        float* target = sel ? g_nm : g_dn;
#pragma unroll
        for (int run = 0; run < 32; run += 16) {
            int base128 = (run >> 4) * 64 + mf * 16;   // row128 of lr=run
            int cur = node_s[base128];
            float acc = 0.f;
#pragma unroll
            for (int k = 0; k < 16; k++) {
                int nd = node_s[base128 + k];
                float v = arr[col_w][run + k];
                if (nd != cur) {
                    if (cur >= 0) atomicAdd(&target[(size_t)cur * HO + col_w], acc);
                    acc = 0.f;
                    cur = nd;
                }
                acc += v;
            }
            if (cur >= 0) atomicAdd(&target[(size_t)cur * HO + col_w], acc);
        }
        __syncthreads();
    }
}

// ---------------- phase 1: single-pass fused GATv2 attention ----------------
// warp per node; deferred normalization: acc = sum ex*feat, rst = acc/den.
__global__ void node_attn_kernel(const float* __restrict__ attn_v) {
    int gid = blockIdx.x * blockDim.x + threadIdx.x;
    int node = gid >> 5;
    int lane = gid & 31;
    if (node >= NN) return;
    int beg = g_off[node], end = g_off[node + 1];

    float fd[HH], av[HH];
#pragma unroll
    for (int h = 0; h < HH; h++) {
        fd[h] = g_feat[(size_t)node * HO + h * OO + lane];
        av[h] = __ldg(&attn_v[h * OO + lane]);
    }

    float den[HH] = {0.f, 0.f, 0.f, 0.f};
    float acc[HH] = {0.f, 0.f, 0.f, 0.f};
    for (int i = beg; i < end; i++) {
        int s = g_srcs[i];
        float f[HH], sc[HH];
#pragma unroll
        for (int h = 0; h < HH; h++) {
            f[h] = g_feat[(size_t)s * HO + h * OO + lane];
            float v = f[h] + fd[h];
            v = v > 0.f ? v : 0.2f * v;
            sc[h] = v * av[h];
        }
#pragma unroll
        for (int off = 16; off; off >>= 1)
#pragma unroll
            for (int h = 0; h < HH; h++) sc[h] += __shfl_xor_sync(0xffffffffu, sc[h], off);
#pragma unroll
        for (int h = 0; h < HH; h++) {
            float ex = __expf(sc[h]);
            den[h] += ex;
            acc[h] += ex * f[h];
        }
    }
#pragma unroll
    for (int h = 0; h < HH; h++) {
        float inv = den[h] > 0.f ? 1.f / den[h] : 0.f;
        int c = h * OO + lane;
        float v = acc[h] * inv + g_res[(size_t)node * HO + c];
        g_h[(size_t)node * HO + c] = v > 0.f ? v : 0.f;
    }
}

// ---------------- final: out = nm/dn; reset accumulators + CSR counters ----------
__global__ void final_kernel(float* __restrict__ out) {
    int i = blockIdx.x * blockDim.x + threadIdx.x;
    if (i < NN * HO) {
        float dn = g_dn[i];
        out[i] = dn > 0.f ? g_nm[i] / dn : 0.f;
        g_dn[i] = 0.f;
        g_nm[i] = 0.f;
    }
    if (i < NN) { g_deg[i] = 0; g_cur[i] = 0; }
}

// ---------------- launch ----------------
extern "C" void kernel_launch(void* const* d_in, const int* in_sizes, int n_in,
                              void* d_out, int out_size) {
    const float* node_feats = (const float*)d_in[0];
    const float* edge_feats = (const float*)d_in[1];
    const int*   src        = (const int*)  d_in[2];
    const int*   dst        = (const int*)  d_in[3];
    const float* W          = (const float*)d_in[4];
    const float* b          = (const float*)d_in[5];
    const float* attn_v     = (const float*)d_in[6];
    const float* Wres       = (const float*)d_in[7];
    const float* bres       = (const float*)d_in[8];
    const float* We         = (const float*)d_in[9];
    const float* be         = (const float*)d_in[10];
    float* out = (float*)d_out;

    void *p_feat, *p_res;
    cudaGetSymbolAddress(&p_feat, g_feat);
    cudaGetSymbolAddress(&p_res,  g_res);

    const int NB_NODE = (NN + 127) / 128;       // 391
    const int NB_EDGE = (EE + 127) / 128;       // 4688
    const int SCAN_BLOCKS = (NN + 255) / 256;   // 196

    count_kernel<<<(EE + 255) / 256, 256>>>(dst);                            // 0
    scan1_kernel<<<SCAN_BLOCKS, 256>>>();                                    // 1
    scan2_kernel<<<1, 256>>>(SCAN_BLOCKS);                                   // 2
    mma_gemm<0><<<NB_NODE, 256>>>(node_feats, W, b, (float*)p_feat, NN, IN_F);   // 3 (profiled)
    mma_gemm<0><<<NB_NODE, 256>>>(node_feats, Wres, bres, (float*)p_res, NN, IN_F); // 4
    scan3_kernel<<<SCAN_BLOCKS, 256>>>();                                    // 5
    scatter_kernel<<<(EE + 255) / 256, 256>>>(dst, src);                     // 6
    node_attn_kernel<<<(NN * 32 + 255) / 256, 256>>>(attn_v);                // 7
    mma_gemm<1><<<NB_EDGE, 256>>>(edge_feats, We, be, nullptr, EE, EF_F);    // 8
    final_kernel<<<(NN * HO + 255) / 256, 256>>>(out);                       // 9
}

// round 9
// speedup vs baseline: 1.5784x; 1.1377x over previous
#include <cuda_runtime.h>
#include <math.h>
#include <float.h>

#define NN 50000
#define EE 600000
#define IN_F 128
#define EF_F 64
#define HH 4
#define OO 32
#define HO 128   // H*O

// ---------------- scratch (device globals: no allocation allowed) ----------------
__device__ float g_feat[NN * HO];          // GATv2 shared projection
__device__ float g_res [NN * HO];          // residual projection
__device__ float g_h   [NN * HO];          // relu(rst + res)
__device__ float g_dn  [NN * HO];          // phase-2 sum exp(m)      (reset by final)
__device__ float g_nm  [NN * HO];          // phase-2 sum m*exp(m)    (reset by final)
// CSR by dst (zero-init at module load; final_kernel restores zeros each run)
__device__ int g_deg[NN];
__device__ int g_cur[NN];
__device__ int g_off[NN + 1];
__device__ int g_eid [EE];                 // CSR position -> edge id
__device__ int g_srcs[EE];                 // CSR position -> src node
__device__ int g_dstc[EE];                 // CSR position -> dst node
__device__ int g_bsum[256];

// ---------------- CSR build ----------------
__global__ void count_kernel(const int* __restrict__ dst) {
    int e = blockIdx.x * blockDim.x + threadIdx.x;
    if (e < EE) atomicAdd(&g_deg[dst[e]], 1);
}

__global__ void scan1_kernel() {
    __shared__ int s[256];
    int t = threadIdx.x;
    int i = blockIdx.x * 256 + t;
    int v = (i < NN) ? g_deg[i] : 0;
    s[t] = v;
    __syncthreads();
#pragma unroll
    for (int o = 1; o < 256; o <<= 1) {
        int x = (t >= o) ? s[t - o] : 0;
        __syncthreads();
        s[t] += x;
        __syncthreads();
    }
    if (i < NN) g_off[i] = s[t] - v;
    if (t == 255) g_bsum[blockIdx.x] = s[255];
}

__global__ void scan2_kernel(int nblocks) {
    __shared__ int s[256];
    int t = threadIdx.x;
    int v = (t < nblocks) ? g_bsum[t] : 0;
    s[t] = v;
    __syncthreads();
#pragma unroll
    for (int o = 1; o < 256; o <<= 1) {
        int x = (t >= o) ? s[t - o] : 0;
        __syncthreads();
        s[t] += x;
        __syncthreads();
    }
    if (t < nblocks) g_bsum[t] = s[t] - v;
}

__global__ void scan3_kernel() {
    int i = blockIdx.x * 256 + threadIdx.x;
    if (i < NN) g_off[i] += g_bsum[blockIdx.x];
    if (i == 0) g_off[NN] = EE;
}

__global__ void scatter_kernel(const int* __restrict__ dst, const int* __restrict__ src) {
    int e = blockIdx.x * blockDim.x + threadIdx.x;
    if (e < EE) {
        int d = dst[e];
        int p = atomicAdd(&g_cur[d], 1);
        int i = g_off[d] + p;
        g_eid[i]  = e;
        g_srcs[i] = src[e];
        g_dstc[i] = d;
    }
}

// ---------------- tf32 GEMM, cp.async 2-stage pipeline, register RNA rounding -----
__device__ __forceinline__ void mma_tf32(float* c, const unsigned* a, const unsigned* b) {
    asm volatile(
        "mma.sync.aligned.m16n8k8.row.col.f32.tf32.tf32.f32 "
        "{%0,%1,%2,%3}, {%4,%5,%6,%7}, {%8,%9}, {%0,%1,%2,%3};\n"
        : "+f"(c[0]), "+f"(c[1]), "+f"(c[2]), "+f"(c[3])
        : "r"(a[0]), "r"(a[1]), "r"(a[2]), "r"(a[3]), "r"(b[0]), "r"(b[1]));
}

__device__ __forceinline__ void cp16(unsigned smem, const void* gptr, int srcsize) {
    asm volatile("cp.async.cg.shared.global [%0], [%1], 16, %2;\n"
                 :: "r"(smem), "l"(gptr), "r"(srcsize));
}

// RNA rounding to tf32 in a register: MMA reads bits [13:31] only; adding
// 0x1000 rounds the magnitude half-away (carry into exponent is correct).
// Bit-identical to cvt.rna.tf32.f32 in the consumed bits.
#define RND(u) ((u) + 0x1000u)

#define RSTRIDE 20                           // floats per smem row (conflict-free, 16B-aligned)
#define TILE_W  (128 * RSTRIDE)              // words per tile
#define STG_BYTES (128 * 33 * 4)             // 16896
#define SMEM_RAW_BYTES (4 * TILE_W * 4)      // 40960 >= 2*STG_BYTES

// DUAL node GEMM (FUSE_EDGE=0): blockIdx.y picks (Wt,bias,C) set; rows plain.
// FUSE_EDGE=1: rows are CSR positions; A row = edge_feats[g_eid[i]];
//   m = acc + bias + g_h[g_srcs[i]]; accumulate exp(m), m*exp(m) into g_dn/g_nm.
template <int FUSE_EDGE>
__global__ __launch_bounds__(256) void mma_gemm(const float* __restrict__ A,
                                                const float* __restrict__ Wt0,
                                                const float* __restrict__ bias0,
                                                float* __restrict__ C0,
                                                const float* __restrict__ Wt1,
                                                const float* __restrict__ bias1,
                                                float* __restrict__ C1,
                                                int M, int K) {
    __shared__ __align__(16) unsigned char s_raw[SMEM_RAW_BYTES];
    unsigned* sAB = reinterpret_cast<unsigned*>(s_raw);
    float (*stg_ex)[33]  = reinterpret_cast<float (*)[33]>(s_raw);
    float (*stg_exm)[33] = reinterpret_cast<float (*)[33]>(s_raw + STG_BYTES);
    __shared__ int eid_s[128];
    __shared__ int node_s[128];

    const float* Wt   = (FUSE_EDGE || blockIdx.y == 0) ? Wt0 : Wt1;
    const float* bias = (FUSE_EDGE || blockIdx.y == 0) ? bias0 : bias1;
    float* C          = (FUSE_EDGE || blockIdx.y == 0) ? C0 : C1;

    int tid  = threadIdx.x;
    int lane = tid & 31;
    int wid  = tid >> 5;
    int g    = lane >> 2;     // 0..7
    int t    = lane & 3;      // 0..3
    int warp_m = (wid >> 2) * 64;   // 0 | 64
    int warp_n = (wid & 3) * 32;    // 0..96
    int bm = blockIdx.x * 128;

    if (FUSE_EDGE) {
        if (tid < 128) {
            int ok = (bm + tid < M);
            eid_s[tid]  = ok ? g_eid[bm + tid] : 0;
            node_s[tid] = ok ? g_dstc[bm + tid] : -1;
        }
        __syncthreads();
    }

    unsigned smem_base = (unsigned)__cvta_generic_to_shared(s_raw);

    float c[4][4][4];
#pragma unroll
    for (int mf = 0; mf < 4; mf++)
#pragma unroll
        for (int nf = 0; nf < 4; nf++)
#pragma unroll
            for (int r = 0; r < 4; r++) c[mf][nf][r] = 0.f;

    const int NPH = K >> 4;

    auto copy_phase = [&](int ph, int buf) {
        int k0 = ph * 16;
        unsigned abase = smem_base + (unsigned)(buf * 2 * TILE_W) * 4u;
        unsigned bbase = abase + (unsigned)TILE_W * 4u;
#pragma unroll
        for (int r = 0; r < 2; r++) {
            int id  = tid + 256 * r;       // 0..511
            int row = id >> 2;             // 0..127
            int kq  = (id & 3) * 4;        // 0,4,8,12
            const float* ga;
            int oksz = 16;
            if (FUSE_EDGE) {
                ga = &A[(size_t)eid_s[row] * K + k0 + kq];
            } else {
                int valid = (bm + row < M);
                ga = &A[(size_t)(valid ? bm + row : 0) * K + k0 + kq];
                oksz = valid ? 16 : 0;
            }
            cp16(abase + (unsigned)(row * RSTRIDE + kq) * 4u, ga, oksz);
            cp16(bbase + (unsigned)(row * RSTRIDE + kq) * 4u,
                 &Wt[(size_t)row * K + k0 + kq], 16);
        }
    };

    copy_phase(0, 0);
    asm volatile("cp.async.commit_group;\n");

    for (int p = 0; p < NPH; p++) {
        int buf = p & 1;
        if (p + 1 < NPH) {
            copy_phase(p + 1, (p + 1) & 1);
            asm volatile("cp.async.commit_group;\n");
            asm volatile("cp.async.wait_group 1;\n");
        } else {
            asm volatile("cp.async.wait_group 0;\n");
        }
        __syncthreads();

        const unsigned* sA = sAB + buf * 2 * TILE_W;
        const unsigned* sB = sA + TILE_W;
#pragma unroll
        for (int ks = 0; ks < 16; ks += 8) {
            unsigned a[4][4], b[4][2];
#pragma unroll
            for (int mf = 0; mf < 4; mf++) {
                int m0 = warp_m + mf * 16 + g;
                a[mf][0] = RND(sA[m0 * RSTRIDE + ks + t]);
                a[mf][1] = RND(sA[(m0 + 8) * RSTRIDE + ks + t]);
                a[mf][2] = RND(sA[m0 * RSTRIDE + ks + t + 4]);
                a[mf][3] = RND(sA[(m0 + 8) * RSTRIDE + ks + t + 4]);
            }
#pragma unroll
            for (int nf = 0; nf < 4; nf++) {
                int n0 = warp_n + nf * 8 + g;
                b[nf][0] = RND(sB[n0 * RSTRIDE + ks + t]);
                b[nf][1] = RND(sB[n0 * RSTRIDE + ks + t + 4]);
            }
#pragma unroll
            for (int mf = 0; mf < 4; mf++)
#pragma unroll
                for (int nf = 0; nf < 4; nf++)
                    mma_tf32(c[mf][nf], a[mf], b[nf]);
        }
        __syncthreads();
    }

    if (!FUSE_EDGE) {
#pragma unroll
        for (int mf = 0; mf < 4; mf++) {
            int r0 = bm + warp_m + mf * 16 + g;
            int r1 = r0 + 8;
#pragma unroll
            for (int nf = 0; nf < 4; nf++) {
                int col = warp_n + nf * 8 + t * 2;
                float2 bb = *(const float2*)&bias[col];
                if (r0 < M) {
                    float2 v = make_float2(c[mf][nf][0] + bb.x, c[mf][nf][1] + bb.y);
                    *(float2*)&C[(size_t)r0 * HO + col] = v;
                }
                if (r1 < M) {
                    float2 v = make_float2(c[mf][nf][2] + bb.x, c[mf][nf][3] + bb.y);
                    *(float2*)&C[(size_t)r1 * HO + col] = v;
                }
            }
        }
        return;
    }

    // ---- fused phase-2 reduction epilogue ----
    int lr0 = (wid >> 2) * 16 + g;
    int lr1 = lr0 + 8;
    int col_w = tid & 127;        // walker column
    int sel   = tid >> 7;         // 0: ex->g_dn, 1: exm->g_nm

#pragma unroll
    for (int mf = 0; mf < 4; mf++) {
        int r0 = bm + warp_m + mf * 16 + g;
        int r1 = r0 + 8;
        const float* h0 = (r0 < M) ? &g_h[(size_t)g_srcs[r0] * HO] : nullptr;
        const float* h1 = (r1 < M) ? &g_h[(size_t)g_srcs[r1] * HO] : nullptr;
#pragma unroll
        for (int nf = 0; nf < 4; nf++) {
            int col = warp_n + nf * 8 + t * 2;
            float2 bb = *(const float2*)&bias[col];
            float ex0x = 0.f, ex0y = 0.f, em0x = 0.f, em0y = 0.f;
            float ex1x = 0.f, ex1y = 0.f, em1x = 0.f, em1y = 0.f;
            if (r0 < M) {
                float2 hv = *(const float2*)&h0[col];
                float mx = c[mf][nf][0] + bb.x + hv.x;
                float my = c[mf][nf][1] + bb.y + hv.y;
                ex0x = __expf(mx); em0x = ex0x * mx;
                ex0y = __expf(my); em0y = ex0y * my;
            }
            if (r1 < M) {
                float2 hv = *(const float2*)&h1[col];
                float mx = c[mf][nf][2] + bb.x + hv.x;
                float my = c[mf][nf][3] + bb.y + hv.y;
                ex1x = __expf(mx); em1x = ex1x * mx;
                ex1y = __expf(my); em1y = ex1y * my;
            }
            stg_ex [col][lr0] = ex0x;  stg_ex [col + 1][lr0] = ex0y;
            stg_exm[col][lr0] = em0x;  stg_exm[col + 1][lr0] = em0y;
            stg_ex [col][lr1] = ex1x;  stg_ex [col + 1][lr1] = ex1y;
            stg_exm[col][lr1] = em1x;  stg_exm[col + 1][lr1] = em1y;
        }
        __syncthreads();

        const float (*arr)[33] = sel ? stg_exm : stg_ex;
        float* target = sel ? g_nm : g_dn;
#pragma unroll
        for (int run = 0; run < 32; run += 16) {
            int base128 = (run >> 4) * 64 + mf * 16;   // row128 of lr=run
            int cur = node_s[base128];
            float acc = 0.f;
#pragma unroll
            for (int k = 0; k < 16; k++) {
                int nd = node_s[base128 + k];
                float v = arr[col_w][run + k];
                if (nd != cur) {
                    if (cur >= 0) atomicAdd(&target[(size_t)cur * HO + col_w], acc);
                    acc = 0.f;
                    cur = nd;
                }
                acc += v;
            }
            if (cur >= 0) atomicAdd(&target[(size_t)cur * HO + col_w], acc);
        }
        __syncthreads();
    }
}

// ---------------- phase 1: single-pass fused GATv2 attention ----------------
__global__ void node_attn_kernel(const float* __restrict__ attn_v) {
    int gid = blockIdx.x * blockDim.x + threadIdx.x;
    int node = gid >> 5;
    int lane = gid & 31;
    if (node >= NN) return;
    int beg = g_off[node], end = g_off[node + 1];

    float fd[HH], av[HH];
#pragma unroll
    for (int h = 0; h < HH; h++) {
        fd[h] = g_feat[(size_t)node * HO + h * OO + lane];
        av[h] = __ldg(&attn_v[h * OO + lane]);
    }

    float den[HH] = {0.f, 0.f, 0.f, 0.f};
    float acc[HH] = {0.f, 0.f, 0.f, 0.f};
    for (int i = beg; i < end; i++) {
        int s = g_srcs[i];
        float f[HH], sc[HH];
#pragma unroll
        for (int h = 0; h < HH; h++) {
            f[h] = g_feat[(size_t)s * HO + h * OO + lane];
            float v = f[h] + fd[h];
            v = v > 0.f ? v : 0.2f * v;
            sc[h] = v * av[h];
        }
#pragma unroll
        for (int off = 16; off; off >>= 1)
#pragma unroll
            for (int h = 0; h < HH; h++) sc[h] += __shfl_xor_sync(0xffffffffu, sc[h], off);
#pragma unroll
        for (int h = 0; h < HH; h++) {
            float ex = __expf(sc[h]);
            den[h] += ex;
            acc[h] += ex * f[h];
        }
    }
#pragma unroll
    for (int h = 0; h < HH; h++) {
        float inv = den[h] > 0.f ? 1.f / den[h] : 0.f;
        int c = h * OO + lane;
        float v = acc[h] * inv + g_res[(size_t)node * HO + c];
        g_h[(size_t)node * HO + c] = v > 0.f ? v : 0.f;
    }
}

// ---------------- final: out = nm/dn; reset accumulators + CSR counters ----------
__global__ void final_kernel(float* __restrict__ out) {
    int i = blockIdx.x * blockDim.x + threadIdx.x;
    if (i < NN * HO) {
        float dn = g_dn[i];
        out[i] = dn > 0.f ? g_nm[i] / dn : 0.f;
        g_dn[i] = 0.f;
        g_nm[i] = 0.f;
    }
    if (i < NN) { g_deg[i] = 0; g_cur[i] = 0; }
}

// ---------------- launch ----------------
extern "C" void kernel_launch(void* const* d_in, const int* in_sizes, int n_in,
                              void* d_out, int out_size) {
    const float* node_feats = (const float*)d_in[0];
    const float* edge_feats = (const float*)d_in[1];
    const int*   src        = (const int*)  d_in[2];
    const int*   dst        = (const int*)  d_in[3];
    const float* W          = (const float*)d_in[4];
    const float* b          = (const float*)d_in[5];
    const float* attn_v     = (const float*)d_in[6];
    const float* Wres       = (const float*)d_in[7];
    const float* bres       = (const float*)d_in[8];
    const float* We         = (const float*)d_in[9];
    const float* be         = (const float*)d_in[10];
    float* out = (float*)d_out;

    void *p_feat, *p_res;
    cudaGetSymbolAddress(&p_feat, g_feat);
    cudaGetSymbolAddress(&p_res,  g_res);

    const int NB_NODE = (NN + 127) / 128;       // 391
    const int NB_EDGE = (EE + 127) / 128;       // 4688
    const int SCAN_BLOCKS = (NN + 255) / 256;   // 196

    count_kernel<<<(EE + 255) / 256, 256>>>(dst);                            // 0
    scan1_kernel<<<SCAN_BLOCKS, 256>>>();                                    // 1
    scan2_kernel<<<1, 256>>>(SCAN_BLOCKS);                                   // 2
    mma_gemm<0><<<dim3(NB_NODE, 2), 256>>>(node_feats, W, b, (float*)p_feat,
                                           Wres, bres, (float*)p_res, NN, IN_F); // 3 (profiled)
    scan3_kernel<<<SCAN_BLOCKS, 256>>>();                                    // 4
    scatter_kernel<<<(EE + 255) / 256, 256>>>(dst, src);                     // 5
    node_attn_kernel<<<(NN * 32 + 255) / 256, 256>>>(attn_v);                // 6
    mma_gemm<1><<<NB_EDGE, 256>>>(edge_feats, We, be, nullptr,
                                  nullptr, nullptr, nullptr, EE, EF_F);      // 7
    final_kernel<<<(NN * HO + 255) / 256, 256>>>(out);                       // 8
}

// round 11
// speedup vs baseline: 1.5926x; 1.0090x over previous
#include <cuda_runtime.h>
#include <math.h>
#include <float.h>

#define NN 50000
#define EE 600000
#define IN_F 128
#define EF_F 64
#define HH 4
#define OO 32
#define HO 128   // H*O

// ---------------- scratch (device globals: no allocation allowed) ----------------
__device__ float g_feat[NN * HO];          // GATv2 shared projection
__device__ float g_res [NN * HO];          // residual projection
__device__ float g_h   [NN * HO];          // relu(rst + res)
__device__ float g_dn  [NN * HO];          // phase-2 sum exp(m)      (reset by final)
__device__ float g_nm  [NN * HO];          // phase-2 sum m*exp(m)    (reset by final)
// CSR by dst (zero-init at module load; final_kernel restores zeros each run)
__device__ int g_deg[NN];
__device__ int g_cur[NN];
__device__ int g_off[NN + 1];
__device__ int g_eid [EE];                 // CSR position -> edge id
__device__ int g_srcs[EE];                 // CSR position -> src node
__device__ int g_dstc[EE];                 // CSR position -> dst node
__device__ int g_bsum[256];

// ---------------- CSR build ----------------
__global__ void count_kernel(const int* __restrict__ dst) {
    int e = blockIdx.x * blockDim.x + threadIdx.x;
    if (e < EE) atomicAdd(&g_deg[dst[e]], 1);
}

__global__ void scan1_kernel() {
    __shared__ int s[256];
    int t = threadIdx.x;
    int i = blockIdx.x * 256 + t;
    int v = (i < NN) ? g_deg[i] : 0;
    s[t] = v;
    __syncthreads();
#pragma unroll
    for (int o = 1; o < 256; o <<= 1) {
        int x = (t >= o) ? s[t - o] : 0;
        __syncthreads();
        s[t] += x;
        __syncthreads();
    }
    if (i < NN) g_off[i] = s[t] - v;
    if (t == 255) g_bsum[blockIdx.x] = s[255];
}

__global__ void scan2_kernel(int nblocks) {
    __shared__ int s[256];
    int t = threadIdx.x;
    int v = (t < nblocks) ? g_bsum[t] : 0;
    s[t] = v;
    __syncthreads();
#pragma unroll
    for (int o = 1; o < 256; o <<= 1) {
        int x = (t >= o) ? s[t - o] : 0;
        __syncthreads();
        s[t] += x;
        __syncthreads();
    }
    if (t < nblocks) g_bsum[t] = s[t] - v;
}

__global__ void scan3_kernel() {
    int i = blockIdx.x * 256 + threadIdx.x;
    if (i < NN) g_off[i] += g_bsum[blockIdx.x];
    if (i == 0) g_off[NN] = EE;
}

__global__ void scatter_kernel(const int* __restrict__ dst, const int* __restrict__ src) {
    int e = blockIdx.x * blockDim.x + threadIdx.x;
    if (e < EE) {
        int d = dst[e];
        int p = atomicAdd(&g_cur[d], 1);
        int i = g_off[d] + p;
        g_eid[i]  = e;
        g_srcs[i] = src[e];
        g_dstc[i] = d;
    }
}

// ---------------- tf32 GEMM: cp.async pipeline + ldmatrix fragments ----------------
__device__ __forceinline__ void mma_tf32(float* c, const unsigned* a, const unsigned* b) {
    asm volatile(
        "mma.sync.aligned.m16n8k8.row.col.f32.tf32.tf32.f32 "
        "{%0,%1,%2,%3}, {%4,%5,%6,%7}, {%8,%9}, {%0,%1,%2,%3};\n"
        : "+f"(c[0]), "+f"(c[1]), "+f"(c[2]), "+f"(c[3])
        : "r"(a[0]), "r"(a[1]), "r"(a[2]), "r"(a[3]), "r"(b[0]), "r"(b[1]));
}

__device__ __forceinline__ void cp16(unsigned smem, const void* gptr, int srcsize) {
    asm volatile("cp.async.cg.shared.global [%0], [%1], 16, %2;\n"
                 :: "r"(smem), "l"(gptr), "r"(srcsize));
}

__device__ __forceinline__ void ldsm_x4(unsigned* r, unsigned addr) {
    asm volatile("ldmatrix.sync.aligned.m8n8.x4.shared.b16 {%0,%1,%2,%3}, [%4];"
                 : "=r"(r[0]), "=r"(r[1]), "=r"(r[2]), "=r"(r[3]) : "r"(addr));
}

__device__ __forceinline__ void ldsm_x2(unsigned* r, unsigned addr) {
    asm volatile("ldmatrix.sync.aligned.m8n8.x2.shared.b16 {%0,%1}, [%2];"
                 : "=r"(r[0]), "=r"(r[1]) : "r"(addr));
}

// RNA rounding to tf32 in a register: MMA reads bits [13:31] only; adding
// 0x1000 rounds half-away with correct carry. Bit-identical to cvt.rna.tf32.
#define RND(u) ((u) + 0x1000u)

#define RSTRIDE 20                           // words per smem row (conflict-free, 16B-aligned)
#define TILE_W  (128 * RSTRIDE)
#define STG_BYTES (128 * 33 * 4)             // 16896
#define SMEM_RAW_BYTES (4 * TILE_W * 4)      // 40960 >= 2*STG_BYTES

// DUAL node GEMM (FUSE_EDGE=0): blockIdx.y picks (Wt,bias,C) set; rows plain.
// FUSE_EDGE=1: rows are CSR positions; A row = edge_feats[g_eid[i]];
//   m = acc + bias + g_h[g_srcs[i]]; accumulate exp(m), m*exp(m) into g_dn/g_nm.
template <int FUSE_EDGE>
__global__ __launch_bounds__(256) void mma_gemm(const float* __restrict__ A,
                                                const float* __restrict__ Wt0,
                                                const float* __restrict__ bias0,
                                                float* __restrict__ C0,
                                                const float* __restrict__ Wt1,
                                                const float* __restrict__ bias1,
                                                float* __restrict__ C1,
                                                int M, int K) {
    __shared__ __align__(16) unsigned char s_raw[SMEM_RAW_BYTES];
    float (*stg_ex)[33]  = reinterpret_cast<float (*)[33]>(s_raw);
    float (*stg_exm)[33] = reinterpret_cast<float (*)[33]>(s_raw + STG_BYTES);
    __shared__ int eid_s[128];
    __shared__ int node_s[128];

    const float* Wt   = (FUSE_EDGE || blockIdx.y == 0) ? Wt0 : Wt1;
    const float* bias = (FUSE_EDGE || blockIdx.y == 0) ? bias0 : bias1;
    float* C          = (FUSE_EDGE || blockIdx.y == 0) ? C0 : C1;

    int tid  = threadIdx.x;
    int lane = tid & 31;
    int wid  = tid >> 5;
    int g    = lane >> 2;     // 0..7
    int t    = lane & 3;      // 0..3
    int warp_m = (wid >> 2) * 64;   // 0 | 64
    int warp_n = (wid & 3) * 32;    // 0..96
    int bm = blockIdx.x * 128;

    if (FUSE_EDGE) {
        if (tid < 128) {
            int ok = (bm + tid < M);
            eid_s[tid]  = ok ? g_eid[bm + tid] : 0;
            node_s[tid] = ok ? g_dstc[bm + tid] : -1;
        }
        __syncthreads();
    }

    unsigned smem_base = (unsigned)__cvta_generic_to_shared(s_raw);

    // ldmatrix lane->row/col selectors
    int aRow = warp_m + (lane & 7) + ((lane >> 3) & 1) * 8;  // + mf*16
    int aK   = (lane >> 4) * 4;                              // + ks
    int bRow = warp_n + (lane & 7);                          // + nf*8
    int bK   = ((lane >> 3) & 1) * 4;                        // + ks

    float c[4][4][4];
#pragma unroll
    for (int mf = 0; mf < 4; mf++)
#pragma unroll
        for (int nf = 0; nf < 4; nf++)
#pragma unroll
            for (int r = 0; r < 4; r++) c[mf][nf][r] = 0.f;

    const int NPH = K >> 4;

    auto copy_phase = [&](int ph, int buf) {
        int k0 = ph * 16;
        unsigned abase = smem_base + (unsigned)(buf * 2 * TILE_W) * 4u;
        unsigned bbase = abase + (unsigned)TILE_W * 4u;
#pragma unroll
        for (int r = 0; r < 2; r++) {
            int id  = tid + 256 * r;       // 0..511
            int row = id >> 2;             // 0..127
            int kq  = (id & 3) * 4;        // 0,4,8,12
            const float* ga;
            int oksz = 16;
            if (FUSE_EDGE) {
                ga = &A[(size_t)eid_s[row] * K + k0 + kq];
            } else {
                int valid = (bm + row < M);
                ga = &A[(size_t)(valid ? bm + row : 0) * K + k0 + kq];
                oksz = valid ? 16 : 0;
            }
            cp16(abase + (unsigned)(row * RSTRIDE + kq) * 4u, ga, oksz);
            cp16(bbase + (unsigned)(row * RSTRIDE + kq) * 4u,
                 &Wt[(size_t)row * K + k0 + kq], 16);
        }
    };

    copy_phase(0, 0);
    asm volatile("cp.async.commit_group;\n");

    for (int p = 0; p < NPH; p++) {
        int buf = p & 1;
        if (p + 1 < NPH) {
            copy_phase(p + 1, (p + 1) & 1);
            asm volatile("cp.async.commit_group;\n");
            asm volatile("cp.async.wait_group 1;\n");
        } else {
            asm volatile("cp.async.wait_group 0;\n");
        }
        __syncthreads();

        unsigned aBase = smem_base + (unsigned)(buf * 2 * TILE_W) * 4u
                       + (unsigned)(aRow * RSTRIDE + aK) * 4u;
        unsigned bBase = smem_base + (unsigned)(buf * 2 * TILE_W + TILE_W) * 4u
                       + (unsigned)(bRow * RSTRIDE + bK) * 4u;
#pragma unroll
        for (int ks = 0; ks < 16; ks += 8) {
            unsigned a[4][4], b[4][2];
#pragma unroll
            for (int mf = 0; mf < 4; mf++)
                ldsm_x4(a[mf], aBase + (unsigned)(mf * 16 * RSTRIDE + ks) * 4u);
#pragma unroll
            for (int nf = 0; nf < 4; nf++)
                ldsm_x2(b[nf], bBase + (unsigned)(nf * 8 * RSTRIDE + ks) * 4u);
#pragma unroll
            for (int mf = 0; mf < 4; mf++)
#pragma unroll
                for (int r = 0; r < 4; r++) a[mf][r] = RND(a[mf][r]);
#pragma unroll
            for (int nf = 0; nf < 4; nf++) {
                b[nf][0] = RND(b[nf][0]);
                b[nf][1] = RND(b[nf][1]);
            }
#pragma unroll
            for (int mf = 0; mf < 4; mf++)
#pragma unroll
                for (int nf = 0; nf < 4; nf++)
                    mma_tf32(c[mf][nf], a[mf], b[nf]);
        }
        __syncthreads();
    }

    if (!FUSE_EDGE) {
#pragma unroll
        for (int mf = 0; mf < 4; mf++) {
            int r0 = bm + warp_m + mf * 16 + g;
            int r1 = r0 + 8;
#pragma unroll
            for (int nf = 0; nf < 4; nf++) {
                int col = warp_n + nf * 8 + t * 2;
                float2 bb = *(const float2*)&bias[col];
                if (r0 < M) {
                    float2 v = make_float2(c[mf][nf][0] + bb.x, c[mf][nf][1] + bb.y);
                    *(float2*)&C[(size_t)r0 * HO + col] = v;
                }
                if (r1 < M) {
                    float2 v = make_float2(c[mf][nf][2] + bb.x, c[mf][nf][3] + bb.y);
                    *(float2*)&C[(size_t)r1 * HO + col] = v;
                }
            }
        }
        return;
    }

    // ---- fused phase-2 reduction epilogue ----
    int lr0 = (wid >> 2) * 16 + g;
    int lr1 = lr0 + 8;
    int col_w = tid & 127;        // walker column
    int sel   = tid >> 7;         // 0: ex->g_dn, 1: exm->g_nm

#pragma unroll
    for (int mf = 0; mf < 4; mf++) {
        int r0 = bm + warp_m + mf * 16 + g;
        int r1 = r0 + 8;
        const float* h0 = (r0 < M) ? &g_h[(size_t)g_srcs[r0] * HO] : nullptr;
        const float* h1 = (r1 < M) ? &g_h[(size_t)g_srcs[r1] * HO] : nullptr;
#pragma unroll
        for (int nf = 0; nf < 4; nf++) {
            int col = warp_n + nf * 8 + t * 2;
            float2 bb = *(const float2*)&bias[col];
            float ex0x = 0.f, ex0y = 0.f, em0x = 0.f, em0y = 0.f;
            float ex1x = 0.f, ex1y = 0.f, em1x = 0.f, em1y = 0.f;
            if (r0 < M) {
                float2 hv = *(const float2*)&h0[col];
                float mx = c[mf][nf][0] + bb.x + hv.x;
                float my = c[mf][nf][1] + bb.y + hv.y;
                ex0x = __expf(mx); em0x = ex0x * mx;
                ex0y = __expf(my); em0y = ex0y * my;
            }
            if (r1 < M) {
                float2 hv = *(const float2*)&h1[col];
                float mx = c[mf][nf][2] + bb.x + hv.x;
                float my = c[mf][nf][3] + bb.y + hv.y;
                ex1x = __expf(mx); em1x = ex1x * mx;
                ex1y = __expf(my); em1y = ex1y * my;
            }
            stg_ex [col][lr0] = ex0x;  stg_ex [col + 1][lr0] = ex0y;
            stg_exm[col][lr0] = em0x;  stg_exm[col + 1][lr0] = em0y;
            stg_ex [col][lr1] = ex1x;  stg_ex [col + 1][lr1] = ex1y;
            stg_exm[col][lr1] = em1x;  stg_exm[col + 1][lr1] = em1y;
        }
        __syncthreads();

        const float (*arr)[33] = sel ? stg_exm : stg_ex;
        float* target = sel ? g_nm : g_dn;
#pragma unroll
        for (int run = 0; run < 32; run += 16) {
            int base128 = (run >> 4) * 64 + mf * 16;   // row128 of lr=run
            int cur = node_s[base128];
            float acc = 0.f;
#pragma unroll
            for (int k = 0; k < 16; k++) {
                int nd = node_s[base128 + k];
                float v = arr[col_w][run + k];
                if (nd != cur) {
                    if (cur >= 0) atomicAdd(&target[(size_t)cur * HO + col_w], acc);
                    acc = 0.f;
                    cur = nd;
                }
                acc += v;
            }
            if (cur >= 0) atomicAdd(&target[(size_t)cur * HO + col_w], acc);
        }
        __syncthreads();
    }
}

// ---------------- phase 1: single-pass fused GATv2 attention ----------------
__global__ void node_attn_kernel(const float* __restrict__ attn_v) {
    int gid = blockIdx.x * blockDim.x + threadIdx.x;
    int node = gid >> 5;
    int lane = gid & 31;
    if (node >= NN) return;
    int beg = g_off[node], end = g_off[node + 1];

    float fd[HH], av[HH];
#pragma unroll
    for (int h = 0; h < HH; h++) {
        fd[h] = g_feat[(size_t)node * HO + h * OO + lane];
        av[h] = __ldg(&attn_v[h * OO + lane]);
    }

    float den[HH] = {0.f, 0.f, 0.f, 0.f};
    float acc[HH] = {0.f, 0.f, 0.f, 0.f};
    for (int i = beg; i < end; i++) {
        int s = g_srcs[i];
        float f[HH], sc[HH];
#pragma unroll
        for (int h = 0; h < HH; h++) {
            f[h] = g_feat[(size_t)s * HO + h * OO + lane];
            float v = f[h] + fd[h];
            v = v > 0.f ? v : 0.2f * v;
            sc[h] = v * av[h];
        }
#pragma unroll
        for (int off = 16; off; off >>= 1)
#pragma unroll
            for (int h = 0; h < HH; h++) sc[h] += __shfl_xor_sync(0xffffffffu, sc[h], off);
#pragma unroll
        for (int h = 0; h < HH; h++) {
            float ex = __expf(sc[h]);
            den[h] += ex;
            acc[h] += ex * f[h];
        }
    }
#pragma unroll
    for (int h = 0; h < HH; h++) {
        float inv = den[h] > 0.f ? 1.f / den[h] : 0.f;
        int c = h * OO + lane;
        float v = acc[h] * inv + g_res[(size_t)node * HO + c];
        g_h[(size_t)node * HO + c] = v > 0.f ? v : 0.f;
    }
}

// ---------------- final: out = nm/dn; reset accumulators + CSR counters ----------
__global__ void final_kernel(float* __restrict__ out) {
    int i = blockIdx.x * blockDim.x + threadIdx.x;
    if (i < NN * HO) {
        float dn = g_dn[i];
        out[i] = dn > 0.f ? g_nm[i] / dn : 0.f;
        g_dn[i] = 0.f;
        g_nm[i] = 0.f;
    }
    if (i < NN) { g_deg[i] = 0; g_cur[i] = 0; }
}

// ---------------- launch ----------------
extern "C" void kernel_launch(void* const* d_in, const int* in_sizes, int n_in,
                              void* d_out, int out_size) {
    const float* node_feats = (const float*)d_in[0];
    const float* edge_feats = (const float*)d_in[1];
    const int*   src        = (const int*)  d_in[2];
    const int*   dst        = (const int*)  d_in[3];
    const float* W          = (const float*)d_in[4];
    const float* b          = (const float*)d_in[5];
    const float* attn_v     = (const float*)d_in[6];
    const float* Wres       = (const float*)d_in[7];
    const float* bres       = (const float*)d_in[8];
    const float* We         = (const float*)d_in[9];
    const float* be         = (const float*)d_in[10];
    float* out = (float*)d_out;

    void *p_feat, *p_res;
    cudaGetSymbolAddress(&p_feat, g_feat);
    cudaGetSymbolAddress(&p_res,  g_res);

    const int NB_NODE = (NN + 127) / 128;       // 391
    const int NB_EDGE = (EE + 127) / 128;       // 4688
    const int SCAN_BLOCKS = (NN + 255) / 256;   // 196

    count_kernel<<<(EE + 255) / 256, 256>>>(dst);                            // 0
    scan1_kernel<<<SCAN_BLOCKS, 256>>>();                                    // 1
    scan2_kernel<<<1, 256>>>(SCAN_BLOCKS);                                   // 2
    mma_gemm<0><<<dim3(NB_NODE, 2), 256>>>(node_feats, W, b, (float*)p_feat,
                                           Wres, bres, (float*)p_res, NN, IN_F); // 3 (profiled)
    scan3_kernel<<<SCAN_BLOCKS, 256>>>();                                    // 4
    scatter_kernel<<<(EE + 255) / 256, 256>>>(dst, src);                     // 5
    node_attn_kernel<<<(NN * 32 + 255) / 256, 256>>>(attn_v);                // 6
    mma_gemm<1><<<NB_EDGE, 256>>>(edge_feats, We, be, nullptr,
                                  nullptr, nullptr, nullptr, EE, EF_F);      // 7
    final_kernel<<<(NN * HO + 255) / 256, 256>>>(out);                       // 8
}

// round 12
// speedup vs baseline: 1.7843x; 1.1204x over previous
#include <cuda_runtime.h>
#include <math.h>
#include <float.h>

#define NN 50000
#define EE 600000
#define IN_F 128
#define EF_F 64
#define HH 4
#define OO 32
#define HO 128   // H*O

// ---------------- scratch (device globals: no allocation allowed) ----------------
__device__ float g_feat[NN * HO];          // GATv2 shared projection
__device__ float g_res [NN * HO];          // residual projection
__device__ float g_h   [NN * HO];          // relu(rst + res)
__device__ float g_dn  [NN * HO];          // phase-2 sum exp(m)      (reset by final)
__device__ float g_nm  [NN * HO];          // phase-2 sum m*exp(m)    (reset by final)
// CSR by dst (zero-init at module load; final_kernel restores zeros each run)
__device__ int g_deg[NN];
__device__ int g_cur[NN];
__device__ int g_off[NN + 1];
__device__ int g_eid [EE];                 // CSR position -> edge id
__device__ int g_srcs[EE];                 // CSR position -> src node
__device__ int g_dstc[EE];                 // CSR position -> dst node
__device__ int g_bsum[256];

// ---------------- CSR build ----------------
__global__ void count_kernel(const int* __restrict__ dst) {
    int e = blockIdx.x * blockDim.x + threadIdx.x;
    if (e < EE) atomicAdd(&g_deg[dst[e]], 1);
}

__global__ void scan1_kernel() {
    __shared__ int s[256];
    int t = threadIdx.x;
    int i = blockIdx.x * 256 + t;
    int v = (i < NN) ? g_deg[i] : 0;
    s[t] = v;
    __syncthreads();
#pragma unroll
    for (int o = 1; o < 256; o <<= 1) {
        int x = (t >= o) ? s[t - o] : 0;
        __syncthreads();
        s[t] += x;
        __syncthreads();
    }
    if (i < NN) g_off[i] = s[t] - v;
    if (t == 255) g_bsum[blockIdx.x] = s[255];
}

__global__ void scan2_kernel(int nblocks) {
    __shared__ int s[256];
    int t = threadIdx.x;
    int v = (t < nblocks) ? g_bsum[t] : 0;
    s[t] = v;
    __syncthreads();
#pragma unroll
    for (int o = 1; o < 256; o <<= 1) {
        int x = (t >= o) ? s[t - o] : 0;
        __syncthreads();
        s[t] += x;
        __syncthreads();
    }
    if (t < nblocks) g_bsum[t] = s[t] - v;
}

__global__ void scan3_kernel() {
    int i = blockIdx.x * 256 + threadIdx.x;
    if (i < NN) g_off[i] += g_bsum[blockIdx.x];
    if (i == 0) g_off[NN] = EE;
}

__global__ void scatter_kernel(const int* __restrict__ dst, const int* __restrict__ src) {
    int e = blockIdx.x * blockDim.x + threadIdx.x;
    if (e < EE) {
        int d = dst[e];
        int p = atomicAdd(&g_cur[d], 1);
        int i = g_off[d] + p;
        g_eid[i]  = e;
        g_srcs[i] = src[e];
        g_dstc[i] = d;
    }
}

// ---------------- tf32 GEMM: cp.async pipeline + ldmatrix fragments ----------------
__device__ __forceinline__ void mma_tf32(float* c, const unsigned* a, const unsigned* b) {
    asm volatile(
        "mma.sync.aligned.m16n8k8.row.col.f32.tf32.tf32.f32 "
        "{%0,%1,%2,%3}, {%4,%5,%6,%7}, {%8,%9}, {%0,%1,%2,%3};\n"
        : "+f"(c[0]), "+f"(c[1]), "+f"(c[2]), "+f"(c[3])
        : "r"(a[0]), "r"(a[1]), "r"(a[2]), "r"(a[3]), "r"(b[0]), "r"(b[1]));
}

__device__ __forceinline__ void cp16(unsigned smem, const void* gptr, int srcsize) {
    asm volatile("cp.async.cg.shared.global [%0], [%1], 16, %2;\n"
                 :: "r"(smem), "l"(gptr), "r"(srcsize));
}

__device__ __forceinline__ void ldsm_x4(unsigned* r, unsigned addr) {
    asm volatile("ldmatrix.sync.aligned.m8n8.x4.shared.b16 {%0,%1,%2,%3}, [%4];"
                 : "=r"(r[0]), "=r"(r[1]), "=r"(r[2]), "=r"(r[3]) : "r"(addr));
}

__device__ __forceinline__ void ldsm_x2(unsigned* r, unsigned addr) {
    asm volatile("ldmatrix.sync.aligned.m8n8.x2.shared.b16 {%0,%1}, [%2];"
                 : "=r"(r[0]), "=r"(r[1]) : "r"(addr));
}

// RNA rounding to tf32 in a register: MMA reads bits [13:31] only; adding
// 0x1000 rounds half-away with correct carry. Bit-identical to cvt.rna.tf32.
#define RND(u) ((u) + 0x1000u)

#define RSTRIDE 20                           // words per smem row (conflict-free, 16B-aligned)
#define TILE_W  (128 * RSTRIDE)
#define STG_BYTES (128 * 33 * 4)             // 16896
#define SMEM_RAW_BYTES (4 * TILE_W * 4)      // 40960 >= 2*STG_BYTES

// DUAL node GEMM (FUSE_EDGE=0): blockIdx.y picks (Wt,bias,C) set; rows plain.
// FUSE_EDGE=1: rows are CSR positions; A row = edge_feats[g_eid[i]];
//   m = acc + bias + g_h[g_srcs[i]]; accumulate exp(m), m*exp(m) into g_dn/g_nm.
template <int FUSE_EDGE>
__global__ __launch_bounds__(256) void mma_gemm(const float* __restrict__ A,
                                                const float* __restrict__ Wt0,
                                                const float* __restrict__ bias0,
                                                float* __restrict__ C0,
                                                const float* __restrict__ Wt1,
                                                const float* __restrict__ bias1,
                                                float* __restrict__ C1,
                                                int M, int K) {
    __shared__ __align__(16) unsigned char s_raw[SMEM_RAW_BYTES];
    float (*stg_ex)[33]  = reinterpret_cast<float (*)[33]>(s_raw);
    float (*stg_exm)[33] = reinterpret_cast<float (*)[33]>(s_raw + STG_BYTES);
    __shared__ int eid_s[128];
    __shared__ int node_s[128];

    const float* Wt   = (FUSE_EDGE || blockIdx.y == 0) ? Wt0 : Wt1;
    const float* bias = (FUSE_EDGE || blockIdx.y == 0) ? bias0 : bias1;
    float* C          = (FUSE_EDGE || blockIdx.y == 0) ? C0 : C1;

    int tid  = threadIdx.x;
    int lane = tid & 31;
    int wid  = tid >> 5;
    int g    = lane >> 2;     // 0..7
    int t    = lane & 3;      // 0..3
    int warp_m = (wid >> 2) * 64;   // 0 | 64
    int warp_n = (wid & 3) * 32;    // 0..96
    int bm = blockIdx.x * 128;

    if (FUSE_EDGE) {
        if (tid < 128) {
            int ok = (bm + tid < M);
            eid_s[tid]  = ok ? g_eid[bm + tid] : 0;
            node_s[tid] = ok ? g_dstc[bm + tid] : -1;
        }
        __syncthreads();
    }

    unsigned smem_base = (unsigned)__cvta_generic_to_shared(s_raw);

    // ldmatrix lane->row/col selectors
    int aRow = warp_m + (lane & 7) + ((lane >> 3) & 1) * 8;  // + mf*16
    int aK   = (lane >> 4) * 4;                              // + ks
    int bRow = warp_n + (lane & 7);                          // + nf*8
    int bK   = ((lane >> 3) & 1) * 4;                        // + ks

    float c[4][4][4];
#pragma unroll
    for (int mf = 0; mf < 4; mf++)
#pragma unroll
        for (int nf = 0; nf < 4; nf++)
#pragma unroll
            for (int r = 0; r < 4; r++) c[mf][nf][r] = 0.f;

    const int NPH = K >> 4;

    auto copy_phase = [&](int ph, int buf) {
        int k0 = ph * 16;
        unsigned abase = smem_base + (unsigned)(buf * 2 * TILE_W) * 4u;
        unsigned bbase = abase + (unsigned)TILE_W * 4u;
#pragma unroll
        for (int r = 0; r < 2; r++) {
            int id  = tid + 256 * r;       // 0..511
            int row = id >> 2;             // 0..127
            int kq  = (id & 3) * 4;        // 0,4,8,12
            const float* ga;
            int oksz = 16;
            if (FUSE_EDGE) {
                ga = &A[(size_t)eid_s[row] * K + k0 + kq];
            } else {
                int valid = (bm + row < M);
                ga = &A[(size_t)(valid ? bm + row : 0) * K + k0 + kq];
                oksz = valid ? 16 : 0;
            }
            cp16(abase + (unsigned)(row * RSTRIDE + kq) * 4u, ga, oksz);
            cp16(bbase + (unsigned)(row * RSTRIDE + kq) * 4u,
                 &Wt[(size_t)row * K + k0 + kq], 16);
        }
    };

    copy_phase(0, 0);
    asm volatile("cp.async.commit_group;\n");

    for (int p = 0; p < NPH; p++) {
        int buf = p & 1;
        if (p + 1 < NPH) {
            copy_phase(p + 1, (p + 1) & 1);
            asm volatile("cp.async.commit_group;\n");
            asm volatile("cp.async.wait_group 1;\n");
        } else {
            asm volatile("cp.async.wait_group 0;\n");
        }
        __syncthreads();

        unsigned aBase = smem_base + (unsigned)(buf * 2 * TILE_W) * 4u
                       + (unsigned)(aRow * RSTRIDE + aK) * 4u;
        unsigned bBase = smem_base + (unsigned)(buf * 2 * TILE_W + TILE_W) * 4u
                       + (unsigned)(bRow * RSTRIDE + bK) * 4u;
#pragma unroll
        for (int ks = 0; ks < 16; ks += 8) {
            unsigned a[4][4], b[4][2];
#pragma unroll
            for (int mf = 0; mf < 4; mf++)
                ldsm_x4(a[mf], aBase + (unsigned)(mf * 16 * RSTRIDE + ks) * 4u);
#pragma unroll
            for (int nf = 0; nf < 4; nf++)
                ldsm_x2(b[nf], bBase + (unsigned)(nf * 8 * RSTRIDE + ks) * 4u);
#pragma unroll
            for (int mf = 0; mf < 4; mf++)
#pragma unroll
                for (int r = 0; r < 4; r++) a[mf][r] = RND(a[mf][r]);
#pragma unroll
            for (int nf = 0; nf < 4; nf++) {
                b[nf][0] = RND(b[nf][0]);
                b[nf][1] = RND(b[nf][1]);
            }
#pragma unroll
            for (int mf = 0; mf < 4; mf++)
#pragma unroll
                for (int nf = 0; nf < 4; nf++)
                    mma_tf32(c[mf][nf], a[mf], b[nf]);
        }
        __syncthreads();
    }

    if (!FUSE_EDGE) {
#pragma unroll
        for (int mf = 0; mf < 4; mf++) {
            int r0 = bm + warp_m + mf * 16 + g;
            int r1 = r0 + 8;
#pragma unroll
            for (int nf = 0; nf < 4; nf++) {
                int col = warp_n + nf * 8 + t * 2;
                float2 bb = *(const float2*)&bias[col];
                if (r0 < M) {
                    float2 v = make_float2(c[mf][nf][0] + bb.x, c[mf][nf][1] + bb.y);
                    *(float2*)&C[(size_t)r0 * HO + col] = v;
                }
                if (r1 < M) {
                    float2 v = make_float2(c[mf][nf][2] + bb.x, c[mf][nf][3] + bb.y);
                    *(float2*)&C[(size_t)r1 * HO + col] = v;
                }
            }
        }
        return;
    }

    // ---- fused phase-2 reduction epilogue ----
    int lr0 = (wid >> 2) * 16 + g;
    int lr1 = lr0 + 8;
    int col_w = tid & 127;        // walker column
    int sel   = tid >> 7;         // 0: ex->g_dn, 1: exm->g_nm

#pragma unroll
    for (int mf = 0; mf < 4; mf++) {
        int r0 = bm + warp_m + mf * 16 + g;
        int r1 = r0 + 8;
        const float* h0 = (r0 < M) ? &g_h[(size_t)g_srcs[r0] * HO] : nullptr;
        const float* h1 = (r1 < M) ? &g_h[(size_t)g_srcs[r1] * HO] : nullptr;
#pragma unroll
        for (int nf = 0; nf < 4; nf++) {
            int col = warp_n + nf * 8 + t * 2;
            float2 bb = *(const float2*)&bias[col];
            float ex0x = 0.f, ex0y = 0.f, em0x = 0.f, em0y = 0.f;
            float ex1x = 0.f, ex1y = 0.f, em1x = 0.f, em1y = 0.f;
            if (r0 < M) {
                float2 hv = *(const float2*)&h0[col];
                float mx = c[mf][nf][0] + bb.x + hv.x;
                float my = c[mf][nf][1] + bb.y + hv.y;
                ex0x = __expf(mx); em0x = ex0x * mx;
                ex0y = __expf(my); em0y = ex0y * my;
            }
            if (r1 < M) {
                float2 hv = *(const float2*)&h1[col];
                float mx = c[mf][nf][2] + bb.x + hv.x;
                float my = c[mf][nf][3] + bb.y + hv.y;
                ex1x = __expf(mx); em1x = ex1x * mx;
                ex1y = __expf(my); em1y = ex1y * my;
            }
            stg_ex [col][lr0] = ex0x;  stg_ex [col + 1][lr0] = ex0y;
            stg_exm[col][lr0] = em0x;  stg_exm[col + 1][lr0] = em0y;
            stg_ex [col][lr1] = ex1x;  stg_ex [col + 1][lr1] = ex1y;
            stg_exm[col][lr1] = em1x;  stg_exm[col + 1][lr1] = em1y;
        }
        __syncthreads();

        const float (*arr)[33] = sel ? stg_exm : stg_ex;
        float* target = sel ? g_nm : g_dn;
#pragma unroll
        for (int run = 0; run < 32; run += 16) {
            int base128 = (run >> 4) * 64 + mf * 16;   // row128 of lr=run
            int cur = node_s[base128];
            float acc = 0.f;
#pragma unroll
            for (int k = 0; k < 16; k++) {
                int nd = node_s[base128 + k];
                float v = arr[col_w][run + k];
                if (nd != cur) {
                    if (cur >= 0) atomicAdd(&target[(size_t)cur * HO + col_w], acc);
                    acc = 0.f;
                    cur = nd;
                }
                acc += v;
            }
            if (cur >= 0) atomicAdd(&target[(size_t)cur * HO + col_w], acc);
        }
        __syncthreads();
    }
}

// ---------------- phase 1: single-pass fused GATv2 attention (float4/lane) --------
// warp per node; lane owns channels 4*lane..4*lane+3 (one head per 8-lane group).
// Per-head dot product closes with a 3-round butterfly within the 8-lane group.
__global__ void node_attn_kernel(const float* __restrict__ attn_v) {
    int gid = blockIdx.x * blockDim.x + threadIdx.x;
    int node = gid >> 5;
    int lane = gid & 31;
    if (node >= NN) return;
    int beg = g_off[node], end = g_off[node + 1];

    const float4* featv = (const float4*)g_feat;   // row stride HO/4 = 32
    float4 fd = featv[node * 32 + lane];
    float4 av = __ldg(&((const float4*)attn_v)[lane]);

    float den = 0.f;
    float4 acc = make_float4(0.f, 0.f, 0.f, 0.f);
    for (int i = beg; i < end; i++) {
        int s = g_srcs[i];
        float4 f = featv[s * 32 + lane];
        float vx = f.x + fd.x; vx = vx > 0.f ? vx : 0.2f * vx;
        float vy = f.y + fd.y; vy = vy > 0.f ? vy : 0.2f * vy;
        float vz = f.z + fd.z; vz = vz > 0.f ? vz : 0.2f * vz;
        float vw = f.w + fd.w; vw = vw > 0.f ? vw : 0.2f * vw;
        float sc = vx * av.x + vy * av.y + vz * av.z + vw * av.w;
        sc += __shfl_xor_sync(0xffffffffu, sc, 1);
        sc += __shfl_xor_sync(0xffffffffu, sc, 2);
        sc += __shfl_xor_sync(0xffffffffu, sc, 4);
        float ex = __expf(sc);
        den += ex;
        acc.x += ex * f.x; acc.y += ex * f.y;
        acc.z += ex * f.z; acc.w += ex * f.w;
    }
    float inv = den > 0.f ? 1.f / den : 0.f;
    float4 r = ((const float4*)g_res)[node * 32 + lane];
    float4 o;
    o.x = fmaxf(acc.x * inv + r.x, 0.f);
    o.y = fmaxf(acc.y * inv + r.y, 0.f);
    o.z = fmaxf(acc.z * inv + r.z, 0.f);
    o.w = fmaxf(acc.w * inv + r.w, 0.f);
    ((float4*)g_h)[node * 32 + lane] = o;
}

// ---------------- final: out = nm/dn (float4); reset accumulators + counters ------
__global__ void final_kernel(float* __restrict__ out) {
    int i = blockIdx.x * blockDim.x + threadIdx.x;
    if (i < NN * HO / 4) {
        float4 dn = ((const float4*)g_dn)[i];
        float4 nm = ((const float4*)g_nm)[i];
        float4 o;
        o.x = dn.x > 0.f ? nm.x / dn.x : 0.f;
        o.y = dn.y > 0.f ? nm.y / dn.y : 0.f;
        o.z = dn.z > 0.f ? nm.z / dn.z : 0.f;
        o.w = dn.w > 0.f ? nm.w / dn.w : 0.f;
        ((float4*)out)[i] = o;
        float4 z = make_float4(0.f, 0.f, 0.f, 0.f);
        ((float4*)g_dn)[i] = z;
        ((float4*)g_nm)[i] = z;
    }
    if (i < NN) { g_deg[i] = 0; g_cur[i] = 0; }
}

// ---------------- launch ----------------
extern "C" void kernel_launch(void* const* d_in, const int* in_sizes, int n_in,
                              void* d_out, int out_size) {
    const float* node_feats = (const float*)d_in[0];
    const float* edge_feats = (const float*)d_in[1];
    const int*   src        = (const int*)  d_in[2];
    const int*   dst        = (const int*)  d_in[3];
    const float* W          = (const float*)d_in[4];
    const float* b          = (const float*)d_in[5];
    const float* attn_v     = (const float*)d_in[6];
    const float* Wres       = (const float*)d_in[7];
    const float* bres       = (const float*)d_in[8];
    const float* We         = (const float*)d_in[9];
    const float* be         = (const float*)d_in[10];
    float* out = (float*)d_out;

    void *p_feat, *p_res;
    cudaGetSymbolAddress(&p_feat, g_feat);
    cudaGetSymbolAddress(&p_res,  g_res);

    const int NB_NODE = (NN + 127) / 128;       // 391
    const int NB_EDGE = (EE + 127) / 128;       // 4688
    const int SCAN_BLOCKS = (NN + 255) / 256;   // 196

    count_kernel<<<(EE + 255) / 256, 256>>>(dst);                            // 0
    scan1_kernel<<<SCAN_BLOCKS, 256>>>();                                    // 1
    scan2_kernel<<<1, 256>>>(SCAN_BLOCKS);                                   // 2
    mma_gemm<0><<<dim3(NB_NODE, 2), 256>>>(node_feats, W, b, (float*)p_feat,
                                           Wres, bres, (float*)p_res, NN, IN_F); // 3 (profiled)
    scan3_kernel<<<SCAN_BLOCKS, 256>>>();                                    // 4
    scatter_kernel<<<(EE + 255) / 256, 256>>>(dst, src);                     // 5
    node_attn_kernel<<<(NN * 32 + 255) / 256, 256>>>(attn_v);                // 6
    mma_gemm<1><<<NB_EDGE, 256>>>(edge_feats, We, be, nullptr,
                                  nullptr, nullptr, nullptr, EE, EF_F);      // 7
    final_kernel<<<(NN * HO / 4 + 255) / 256, 256>>>(out);                   // 8
}

// round 13
// speedup vs baseline: 1.8019x; 1.0098x over previous
#include <cuda_runtime.h>
#include <math.h>
#include <float.h>

#define NN 50000
#define EE 600000
#define IN_F 128
#define EF_F 64
#define HH 4
#define OO 32
#define HO 128   // H*O

// ---------------- scratch (device globals: no allocation allowed) ----------------
__device__ float g_feat[NN * HO];          // GATv2 shared projection
__device__ float g_res [NN * HO];          // residual projection
__device__ float g_h   [NN * HO];          // relu(rst + res)
__device__ float g_dn  [NN * HO];          // phase-2 sum exp(m)      (reset by final)
__device__ float g_nm  [NN * HO];          // phase-2 sum m*exp(m)    (reset by final)
// CSR by dst (zero-init at module load; final_kernel restores zeros each run)
__device__ int g_deg[NN];
__device__ int g_cur[NN];
__device__ int g_off[NN + 1];
__device__ int g_eid [EE];                 // CSR position -> edge id
__device__ int g_srcs[EE];                 // CSR position -> src node
__device__ int g_dstc[EE];                 // CSR position -> dst node
__device__ int g_bsum[256];

// ---------------- CSR build ----------------
__global__ void count_kernel(const int* __restrict__ dst) {
    int e = blockIdx.x * blockDim.x + threadIdx.x;
    if (e < EE) atomicAdd(&g_deg[dst[e]], 1);
}

__global__ void scan1_kernel() {
    __shared__ int s[256];
    int t = threadIdx.x;
    int i = blockIdx.x * 256 + t;
    int v = (i < NN) ? g_deg[i] : 0;
    s[t] = v;
    __syncthreads();
#pragma unroll
    for (int o = 1; o < 256; o <<= 1) {
        int x = (t >= o) ? s[t - o] : 0;
        __syncthreads();
        s[t] += x;
        __syncthreads();
    }
    if (i < NN) g_off[i] = s[t] - v;
    if (t == 255) g_bsum[blockIdx.x] = s[255];
}

__global__ void scan2_kernel(int nblocks) {
    __shared__ int s[256];
    int t = threadIdx.x;
    int v = (t < nblocks) ? g_bsum[t] : 0;
    s[t] = v;
    __syncthreads();
#pragma unroll
    for (int o = 1; o < 256; o <<= 1) {
        int x = (t >= o) ? s[t - o] : 0;
        __syncthreads();
        s[t] += x;
        __syncthreads();
    }
    if (t < nblocks) g_bsum[t] = s[t] - v;
}

__global__ void scan3_kernel() {
    int i = blockIdx.x * 256 + threadIdx.x;
    if (i < NN) g_off[i] += g_bsum[blockIdx.x];
    if (i == 0) g_off[NN] = EE;
}

__global__ void scatter_kernel(const int* __restrict__ dst, const int* __restrict__ src) {
    int e = blockIdx.x * blockDim.x + threadIdx.x;
    if (e < EE) {
        int d = dst[e];
        int p = atomicAdd(&g_cur[d], 1);
        int i = g_off[d] + p;
        g_eid[i]  = e;
        g_srcs[i] = src[e];
        g_dstc[i] = d;
    }
}

// ---------------- tf32 GEMM: cp.async pipeline + ldmatrix fragments ----------------
__device__ __forceinline__ void mma_tf32(float* c, const unsigned* a, const unsigned* b) {
    asm volatile(
        "mma.sync.aligned.m16n8k8.row.col.f32.tf32.tf32.f32 "
        "{%0,%1,%2,%3}, {%4,%5,%6,%7}, {%8,%9}, {%0,%1,%2,%3};\n"
        : "+f"(c[0]), "+f"(c[1]), "+f"(c[2]), "+f"(c[3])
        : "r"(a[0]), "r"(a[1]), "r"(a[2]), "r"(a[3]), "r"(b[0]), "r"(b[1]));
}

__device__ __forceinline__ void cp16(unsigned smem, const void* gptr, int srcsize) {
    asm volatile("cp.async.cg.shared.global [%0], [%1], 16, %2;\n"
                 :: "r"(smem), "l"(gptr), "r"(srcsize));
}

__device__ __forceinline__ void ldsm_x4(unsigned* r, unsigned addr) {
    asm volatile("ldmatrix.sync.aligned.m8n8.x4.shared.b16 {%0,%1,%2,%3}, [%4];"
                 : "=r"(r[0]), "=r"(r[1]), "=r"(r[2]), "=r"(r[3]) : "r"(addr));
}

__device__ __forceinline__ void ldsm_x2(unsigned* r, unsigned addr) {
    asm volatile("ldmatrix.sync.aligned.m8n8.x2.shared.b16 {%0,%1}, [%2];"
                 : "=r"(r[0]), "=r"(r[1]) : "r"(addr));
}

// RNA rounding to tf32 in a register: MMA reads bits [13:31] only; adding
// 0x1000 rounds half-away with correct carry. Bit-identical to cvt.rna.tf32.
#define RND(u) ((u) + 0x1000u)

#define RSTRIDE 20                           // words per smem row (conflict-free, 16B-aligned)
#define TILE_W  (128 * RSTRIDE)
#define STG_BYTES (128 * 33 * 4)             // 16896
#define SMEM_RAW_BYTES (4 * TILE_W * 4)      // 40960 >= 2*STG_BYTES

// DUAL node GEMM (FUSE_EDGE=0): blockIdx.y picks (Wt,bias,C) set; rows plain.
// FUSE_EDGE=1: rows are CSR positions; A row = edge_feats[g_eid[i]];
//   m = acc + bias + g_h[g_srcs[i]]; accumulate exp(m), m*exp(m) into g_dn/g_nm.
template <int FUSE_EDGE>
__global__ __launch_bounds__(256) void mma_gemm(const float* __restrict__ A,
                                                const float* __restrict__ Wt0,
                                                const float* __restrict__ bias0,
                                                float* __restrict__ C0,
                                                const float* __restrict__ Wt1,
                                                const float* __restrict__ bias1,
                                                float* __restrict__ C1,
                                                int M, int K) {
    __shared__ __align__(16) unsigned char s_raw[SMEM_RAW_BYTES];
    float (*stg_ex)[33]  = reinterpret_cast<float (*)[33]>(s_raw);
    float (*stg_exm)[33] = reinterpret_cast<float (*)[33]>(s_raw + STG_BYTES);
    __shared__ int eid_s[128];
    __shared__ int node_s[128];

    const float* Wt   = (FUSE_EDGE || blockIdx.y == 0) ? Wt0 : Wt1;
    const float* bias = (FUSE_EDGE || blockIdx.y == 0) ? bias0 : bias1;
    float* C          = (FUSE_EDGE || blockIdx.y == 0) ? C0 : C1;

    int tid  = threadIdx.x;
    int lane = tid & 31;
    int wid  = tid >> 5;
    int g    = lane >> 2;     // 0..7
    int t    = lane & 3;      // 0..3
    int warp_m = (wid >> 2) * 64;   // 0 | 64
    int warp_n = (wid & 3) * 32;    // 0..96
    int bm = blockIdx.x * 128;

    if (FUSE_EDGE) {
        if (tid < 128) {
            int ok = (bm + tid < M);
            eid_s[tid]  = ok ? g_eid[bm + tid] : 0;
            node_s[tid] = ok ? g_dstc[bm + tid] : -1;
        }
        __syncthreads();
    }

    unsigned smem_base = (unsigned)__cvta_generic_to_shared(s_raw);

    // ldmatrix lane->row/col selectors
    int aRow = warp_m + (lane & 7) + ((lane >> 3) & 1) * 8;  // + mf*16
    int aK   = (lane >> 4) * 4;                              // + ks
    int bRow = warp_n + (lane & 7);                          // + nf*8
    int bK   = ((lane >> 3) & 1) * 4;                        // + ks

    float c[4][4][4];
#pragma unroll
    for (int mf = 0; mf < 4; mf++)
#pragma unroll
        for (int nf = 0; nf < 4; nf++)
#pragma unroll
            for (int r = 0; r < 4; r++) c[mf][nf][r] = 0.f;

    const int NPH = K >> 4;

    auto copy_phase = [&](int ph, int buf) {
        int k0 = ph * 16;
        unsigned abase = smem_base + (unsigned)(buf * 2 * TILE_W) * 4u;
        unsigned bbase = abase + (unsigned)TILE_W * 4u;
#pragma unroll
        for (int r = 0; r < 2; r++) {
            int id  = tid + 256 * r;       // 0..511
            int row = id >> 2;             // 0..127
            int kq  = (id & 3) * 4;        // 0,4,8,12
            const float* ga;
            int oksz = 16;
            if (FUSE_EDGE) {
                ga = &A[(size_t)eid_s[row] * K + k0 + kq];
            } else {
                int valid = (bm + row < M);
                ga = &A[(size_t)(valid ? bm + row : 0) * K + k0 + kq];
                oksz = valid ? 16 : 0;
            }
            cp16(abase + (unsigned)(row * RSTRIDE + kq) * 4u, ga, oksz);
            cp16(bbase + (unsigned)(row * RSTRIDE + kq) * 4u,
                 &Wt[(size_t)row * K + k0 + kq], 16);
        }
    };

    copy_phase(0, 0);
    asm volatile("cp.async.commit_group;\n");

    for (int p = 0; p < NPH; p++) {
        int buf = p & 1;
        if (p + 1 < NPH) {
            copy_phase(p + 1, (p + 1) & 1);
            asm volatile("cp.async.commit_group;\n");
            asm volatile("cp.async.wait_group 1;\n");
        } else {
            asm volatile("cp.async.wait_group 0;\n");
        }
        __syncthreads();

        unsigned aBase = smem_base + (unsigned)(buf * 2 * TILE_W) * 4u
                       + (unsigned)(aRow * RSTRIDE + aK) * 4u;
        unsigned bBase = smem_base + (unsigned)(buf * 2 * TILE_W + TILE_W) * 4u
                       + (unsigned)(bRow * RSTRIDE + bK) * 4u;
#pragma unroll
        for (int ks = 0; ks < 16; ks += 8) {
            unsigned a[4][4], b[4][2];
#pragma unroll
            for (int mf = 0; mf < 4; mf++)
                ldsm_x4(a[mf], aBase + (unsigned)(mf * 16 * RSTRIDE + ks) * 4u);
#pragma unroll
            for (int nf = 0; nf < 4; nf++)
                ldsm_x2(b[nf], bBase + (unsigned)(nf * 8 * RSTRIDE + ks) * 4u);
#pragma unroll
            for (int mf = 0; mf < 4; mf++)
#pragma unroll
                for (int r = 0; r < 4; r++) a[mf][r] = RND(a[mf][r]);
#pragma unroll
            for (int nf = 0; nf < 4; nf++) {
                b[nf][0] = RND(b[nf][0]);
                b[nf][1] = RND(b[nf][1]);
            }
#pragma unroll
            for (int mf = 0; mf < 4; mf++)
#pragma unroll
                for (int nf = 0; nf < 4; nf++)
                    mma_tf32(c[mf][nf], a[mf], b[nf]);
        }
        __syncthreads();
    }

    if (!FUSE_EDGE) {
#pragma unroll
        for (int mf = 0; mf < 4; mf++) {
            int r0 = bm + warp_m + mf * 16 + g;
            int r1 = r0 + 8;
#pragma unroll
            for (int nf = 0; nf < 4; nf++) {
                int col = warp_n + nf * 8 + t * 2;
                float2 bb = *(const float2*)&bias[col];
                if (r0 < M) {
                    float2 v = make_float2(c[mf][nf][0] + bb.x, c[mf][nf][1] + bb.y);
                    *(float2*)&C[(size_t)r0 * HO + col] = v;
                }
                if (r1 < M) {
                    float2 v = make_float2(c[mf][nf][2] + bb.x, c[mf][nf][3] + bb.y);
                    *(float2*)&C[(size_t)r1 * HO + col] = v;
                }
            }
        }
        return;
    }

    // ---- fused phase-2 reduction epilogue ----
    int lr0 = (wid >> 2) * 16 + g;
    int lr1 = lr0 + 8;
    int col_w = tid & 127;        // walker column
    int sel   = tid >> 7;         // 0: ex->g_dn, 1: exm->g_nm

#pragma unroll
    for (int mf = 0; mf < 4; mf++) {
        int r0 = bm + warp_m + mf * 16 + g;
        int r1 = r0 + 8;
        const float* h0 = (r0 < M) ? &g_h[(size_t)g_srcs[r0] * HO] : nullptr;
        const float* h1 = (r1 < M) ? &g_h[(size_t)g_srcs[r1] * HO] : nullptr;
#pragma unroll
        for (int nf = 0; nf < 4; nf++) {
            int col = warp_n + nf * 8 + t * 2;
            float2 bb = *(const float2*)&bias[col];
            float ex0x = 0.f, ex0y = 0.f, em0x = 0.f, em0y = 0.f;
            float ex1x = 0.f, ex1y = 0.f, em1x = 0.f, em1y = 0.f;
            if (r0 < M) {
                float2 hv = *(const float2*)&h0[col];
                float mx = c[mf][nf][0] + bb.x + hv.x;
                float my = c[mf][nf][1] + bb.y + hv.y;
                ex0x = __expf(mx); em0x = ex0x * mx;
                ex0y = __expf(my); em0y = ex0y * my;
            }
            if (r1 < M) {
                float2 hv = *(const float2*)&h1[col];
                float mx = c[mf][nf][2] + bb.x + hv.x;
                float my = c[mf][nf][3] + bb.y + hv.y;
                ex1x = __expf(mx); em1x = ex1x * mx;
                ex1y = __expf(my); em1y = ex1y * my;
            }
            stg_ex [col][lr0] = ex0x;  stg_ex [col + 1][lr0] = ex0y;
            stg_exm[col][lr0] = em0x;  stg_exm[col + 1][lr0] = em0y;
            stg_ex [col][lr1] = ex1x;  stg_ex [col + 1][lr1] = ex1y;
            stg_exm[col][lr1] = em1x;  stg_exm[col + 1][lr1] = em1y;
        }
        __syncthreads();

        const float (*arr)[33] = sel ? stg_exm : stg_ex;
        float* target = sel ? g_nm : g_dn;
#pragma unroll
        for (int run = 0; run < 32; run += 16) {
            int base128 = (run >> 4) * 64 + mf * 16;   // row128 of lr=run
            int cur = node_s[base128];
            float acc = 0.f;
#pragma unroll
            for (int k = 0; k < 16; k++) {
                int nd = node_s[base128 + k];
                float v = arr[col_w][run + k];
                if (nd != cur) {
                    if (cur >= 0) atomicAdd(&target[(size_t)cur * HO + col_w], acc);
                    acc = 0.f;
                    cur = nd;
                }
                acc += v;
            }
            if (cur >= 0) atomicAdd(&target[(size_t)cur * HO + col_w], acc);
        }
        __syncthreads();
    }
}

// ---------------- phase 1: single-pass fused GATv2 attention (float4/lane) --------
__global__ void node_attn_kernel(const float* __restrict__ attn_v) {
    int gid = blockIdx.x * blockDim.x + threadIdx.x;
    int node = gid >> 5;
    int lane = gid & 31;
    if (node >= NN) return;
    int beg = g_off[node], end = g_off[node + 1];

    const float4* featv = (const float4*)g_feat;   // row stride HO/4 = 32
    float4 fd = featv[node * 32 + lane];
    float4 av = __ldg(&((const float4*)attn_v)[lane]);

    float den = 0.f;
    float4 acc = make_float4(0.f, 0.f, 0.f, 0.f);
    for (int i = beg; i < end; i++) {
        int s = g_srcs[i];
        float4 f = featv[s * 32 + lane];
        float vx = f.x + fd.x; vx = vx > 0.f ? vx : 0.2f * vx;
        float vy = f.y + fd.y; vy = vy > 0.f ? vy : 0.2f * vy;
        float vz = f.z + fd.z; vz = vz > 0.f ? vz : 0.2f * vz;
        float vw = f.w + fd.w; vw = vw > 0.f ? vw : 0.2f * vw;
        float sc = vx * av.x + vy * av.y + vz * av.z + vw * av.w;
        sc += __shfl_xor_sync(0xffffffffu, sc, 1);
        sc += __shfl_xor_sync(0xffffffffu, sc, 2);
        sc += __shfl_xor_sync(0xffffffffu, sc, 4);
        float ex = __expf(sc);
        den += ex;
        acc.x += ex * f.x; acc.y += ex * f.y;
        acc.z += ex * f.z; acc.w += ex * f.w;
    }
    float inv = den > 0.f ? 1.f / den : 0.f;
    float4 r = ((const float4*)g_res)[node * 32 + lane];
    float4 o;
    o.x = fmaxf(acc.x * inv + r.x, 0.f);
    o.y = fmaxf(acc.y * inv + r.y, 0.f);
    o.z = fmaxf(acc.z * inv + r.z, 0.f);
    o.w = fmaxf(acc.w * inv + r.w, 0.f);
    ((float4*)g_h)[node * 32 + lane] = o;
}

// ---------------- final: out = nm/dn (float4); reset accumulators + counters ------
__global__ void final_kernel(float* __restrict__ out) {
    int i = blockIdx.x * blockDim.x + threadIdx.x;
    if (i < NN * HO / 4) {
        float4 dn = ((const float4*)g_dn)[i];
        float4 nm = ((const float4*)g_nm)[i];
        float4 o;
        o.x = dn.x > 0.f ? nm.x / dn.x : 0.f;
        o.y = dn.y > 0.f ? nm.y / dn.y : 0.f;
        o.z = dn.z > 0.f ? nm.z / dn.z : 0.f;
        o.w = dn.w > 0.f ? nm.w / dn.w : 0.f;
        ((float4*)out)[i] = o;
        float4 z = make_float4(0.f, 0.f, 0.f, 0.f);
        ((float4*)g_dn)[i] = z;
        ((float4*)g_nm)[i] = z;
    }
    if (i < NN) { g_deg[i] = 0; g_cur[i] = 0; }
}

// ---------------- streams/events: hardened ctor, graceful serial fallback ---------
static cudaStream_t g_s2 = nullptr;
static cudaEvent_t  g_evF = nullptr, g_evJ = nullptr;
static struct StreamInit {
    StreamInit() {
        cudaStream_t s = nullptr;
        cudaEvent_t  e1 = nullptr, e2 = nullptr;
        if (cudaStreamCreateWithFlags(&s, cudaStreamNonBlocking) != cudaSuccess) return;
        if (cudaEventCreateWithFlags(&e1, cudaEventDisableTiming) != cudaSuccess) return;
        if (cudaEventCreateWithFlags(&e2, cudaEventDisableTiming) != cudaSuccess) return;
        g_s2 = s; g_evF = e1; g_evJ = e2;
    }
} g_si;

// ---------------- launch ----------------
extern "C" void kernel_launch(void* const* d_in, const int* in_sizes, int n_in,
                              void* d_out, int out_size) {
    const float* node_feats = (const float*)d_in[0];
    const float* edge_feats = (const float*)d_in[1];
    const int*   src        = (const int*)  d_in[2];
    const int*   dst        = (const int*)  d_in[3];
    const float* W          = (const float*)d_in[4];
    const float* b          = (const float*)d_in[5];
    const float* attn_v     = (const float*)d_in[6];
    const float* Wres       = (const float*)d_in[7];
    const float* bres       = (const float*)d_in[8];
    const float* We         = (const float*)d_in[9];
    const float* be         = (const float*)d_in[10];
    float* out = (float*)d_out;

    void *p_feat, *p_res;
    cudaGetSymbolAddress(&p_feat, g_feat);
    cudaGetSymbolAddress(&p_res,  g_res);

    const int NB_NODE = (NN + 127) / 128;       // 391
    const int NB_EDGE = (EE + 127) / 128;       // 4688
    const int SCAN_BLOCKS = (NN + 255) / 256;   // 196

    bool dual = (g_s2 != nullptr);
    cudaStream_t sC = dual ? g_s2 : (cudaStream_t)0;  // CSR chain stream

    if (dual) {
        // fork: CSR chain runs concurrently with the node GEMM pair
        cudaEventRecord(g_evF, 0);
        cudaStreamWaitEvent(sC, g_evF, 0);
    }

    count_kernel<<<(EE + 255) / 256, 256, 0, sC>>>(dst);
    scan1_kernel<<<SCAN_BLOCKS, 256, 0, sC>>>();
    scan2_kernel<<<1, 256, 0, sC>>>(SCAN_BLOCKS);
    scan3_kernel<<<SCAN_BLOCKS, 256, 0, sC>>>();
    scatter_kernel<<<(EE + 255) / 256, 256, 0, sC>>>(dst, src);

    mma_gemm<0><<<dim3(NB_NODE, 2), 256>>>(node_feats, W, b, (float*)p_feat,
                                           Wres, bres, (float*)p_res, NN, IN_F);

    if (dual) {
        // join: node_attn needs g_feat/g_res (stream 0) AND the CSR (sC)
        cudaEventRecord(g_evJ, sC);
        cudaStreamWaitEvent(0, g_evJ, 0);
    }

    node_attn_kernel<<<(NN * 32 + 255) / 256, 256>>>(attn_v);
    mma_gemm<1><<<NB_EDGE, 256>>>(edge_feats, We, be, nullptr,
                                  nullptr, nullptr, nullptr, EE, EF_F);
    final_kernel<<<(NN * HO / 4 + 255) / 256, 256>>>(out);
}

// round 15
// speedup vs baseline: 1.8550x; 1.0295x over previous
#include <cuda_runtime.h>
#include <math.h>
#include <float.h>

#define NN 50000
#define EE 600000
#define IN_F 128
#define EF_F 64
#define HH 4
#define OO 32
#define HO 128   // H*O

// ---------------- scratch (device globals: no allocation allowed) ----------------
__device__ float g_feat[NN * HO];          // GATv2 shared projection
__device__ float g_res [NN * HO];          // residual projection
__device__ float g_h   [NN * HO];          // relu(rst + res)
__device__ float g_dn  [NN * HO];          // phase-2 sum exp(m)      (reset by final)
__device__ float g_nm  [NN * HO];          // phase-2 sum m*exp(m)    (reset by final)
// CSR by dst (zero-init at module load; final_kernel restores zeros each run)
__device__ int g_deg[NN];
__device__ int g_cur[NN];
__device__ int g_off[NN + 1];
__device__ int g_eid [EE];                 // CSR position -> edge id
__device__ int g_srcs[EE];                 // CSR position -> src node
__device__ int g_dstc[EE];                 // CSR position -> dst node
__device__ int g_bsum[256];

// ---------------- CSR build ----------------
__global__ void count_kernel(const int* __restrict__ dst) {
    int e = blockIdx.x * blockDim.x + threadIdx.x;
    if (e < EE) atomicAdd(&g_deg[dst[e]], 1);
}

__global__ void scan1_kernel() {
    __shared__ int s[256];
    int t = threadIdx.x;
    int i = blockIdx.x * 256 + t;
    int v = (i < NN) ? g_deg[i] : 0;
    s[t] = v;
    __syncthreads();
#pragma unroll
    for (int o = 1; o < 256; o <<= 1) {
        int x = (t >= o) ? s[t - o] : 0;
        __syncthreads();
        s[t] += x;
        __syncthreads();
    }
    if (i < NN) g_off[i] = s[t] - v;
    if (t == 255) g_bsum[blockIdx.x] = s[255];
}

__global__ void scan2_kernel(int nblocks) {
    __shared__ int s[256];
    int t = threadIdx.x;
    int v = (t < nblocks) ? g_bsum[t] : 0;
    s[t] = v;
    __syncthreads();
#pragma unroll
    for (int o = 1; o < 256; o <<= 1) {
        int x = (t >= o) ? s[t - o] : 0;
        __syncthreads();
        s[t] += x;
        __syncthreads();
    }
    if (t < nblocks) g_bsum[t] = s[t] - v;
}

__global__ void scan3_kernel() {
    int i = blockIdx.x * 256 + threadIdx.x;
    if (i < NN) g_off[i] += g_bsum[blockIdx.x];
    if (i == 0) g_off[NN] = EE;
}

__global__ void scatter_kernel(const int* __restrict__ dst, const int* __restrict__ src) {
    int e = blockIdx.x * blockDim.x + threadIdx.x;
    if (e < EE) {
        int d = dst[e];
        int p = atomicAdd(&g_cur[d], 1);
        int i = g_off[d] + p;
        g_eid[i]  = e;
        g_srcs[i] = src[e];
        g_dstc[i] = d;
    }
}

// ---------------- tf32 GEMM: cp.async pipeline + ldmatrix fragments ----------------
__device__ __forceinline__ void mma_tf32(float* c, const unsigned* a, const unsigned* b) {
    asm volatile(
        "mma.sync.aligned.m16n8k8.row.col.f32.tf32.tf32.f32 "
        "{%0,%1,%2,%3}, {%4,%5,%6,%7}, {%8,%9}, {%0,%1,%2,%3};\n"
        : "+f"(c[0]), "+f"(c[1]), "+f"(c[2]), "+f"(c[3])
        : "r"(a[0]), "r"(a[1]), "r"(a[2]), "r"(a[3]), "r"(b[0]), "r"(b[1]));
}

__device__ __forceinline__ void cp16(unsigned smem, const void* gptr, int srcsize) {
    asm volatile("cp.async.cg.shared.global [%0], [%1], 16, %2;\n"
                 :: "r"(smem), "l"(gptr), "r"(srcsize));
}

__device__ __forceinline__ void ldsm_x4(unsigned* r, unsigned addr) {
    asm volatile("ldmatrix.sync.aligned.m8n8.x4.shared.b16 {%0,%1,%2,%3}, [%4];"
                 : "=r"(r[0]), "=r"(r[1]), "=r"(r[2]), "=r"(r[3]) : "r"(addr));
}

__device__ __forceinline__ void ldsm_x2(unsigned* r, unsigned addr) {
    asm volatile("ldmatrix.sync.aligned.m8n8.x2.shared.b16 {%0,%1}, [%2];"
                 : "=r"(r[0]), "=r"(r[1]) : "r"(addr));
}

// RNA rounding to tf32 in a register: MMA reads bits [13:31] only; adding
// 0x1000 rounds half-away with correct carry. Bit-identical to cvt.rna.tf32.
#define RND(u) ((u) + 0x1000u)

#define RSTRIDE 20                           // words per smem row (conflict-free, 16B-aligned)
#define TILE_W  (128 * RSTRIDE)
#define STG_BYTES (128 * 33 * 4)             // 16896
#define SMEM_RAW_BYTES (4 * TILE_W * 4)      // 40960 >= 2*STG_BYTES

// DUAL node GEMM (FUSE_EDGE=0): blockIdx.y picks (Wt,bias,C) set; rows plain.
// FUSE_EDGE=1: rows are CSR positions; A row = edge_feats[g_eid[i]];
//   m = acc + bias + g_h[g_srcs[i]]; accumulate exp(m), m*exp(m) into g_dn/g_nm.
template <int FUSE_EDGE>
__global__ __launch_bounds__(256, 3) void mma_gemm(const float* __restrict__ A,
                                                   const float* __restrict__ Wt0,
                                                   const float* __restrict__ bias0,
                                                   float* __restrict__ C0,
                                                   const float* __restrict__ Wt1,
                                                   const float* __restrict__ bias1,
                                                   float* __restrict__ C1,
                                                   int M, int K) {
    __shared__ __align__(16) unsigned char s_raw[SMEM_RAW_BYTES];
    float (*stg_ex)[33]  = reinterpret_cast<float (*)[33]>(s_raw);
    float (*stg_exm)[33] = reinterpret_cast<float (*)[33]>(s_raw + STG_BYTES);
    __shared__ int eid_s[128];
    __shared__ int node_s[128];

    const float* Wt   = (FUSE_EDGE || blockIdx.y == 0) ? Wt0 : Wt1;
    const float* bias = (FUSE_EDGE || blockIdx.y == 0) ? bias0 : bias1;
    float* C          = (FUSE_EDGE || blockIdx.y == 0) ? C0 : C1;

    int tid  = threadIdx.x;
    int lane = tid & 31;
    int wid  = tid >> 5;
    int g    = lane >> 2;     // 0..7
    int t    = lane & 3;      // 0..3
    int warp_m = (wid >> 2) * 64;   // 0 | 64
    int warp_n = (wid & 3) * 32;    // 0..96
    int bm = blockIdx.x * 128;

    if (FUSE_EDGE) {
        if (tid < 128) {
            int ok = (bm + tid < M);
            eid_s[tid]  = ok ? g_eid[bm + tid] : 0;
            node_s[tid] = ok ? g_dstc[bm + tid] : -1;
        }
        __syncthreads();
    }

    unsigned smem_base = (unsigned)__cvta_generic_to_shared(s_raw);

    // ldmatrix lane->row/col selectors
    int aRow = warp_m + (lane & 7) + ((lane >> 3) & 1) * 8;  // + mf*16
    int aK   = (lane >> 4) * 4;                              // + ks
    int bRow = warp_n + (lane & 7);                          // + nf*8
    int bK   = ((lane >> 3) & 1) * 4;                        // + ks

    float c[4][4][4];
#pragma unroll
    for (int mf = 0; mf < 4; mf++)
#pragma unroll
        for (int nf = 0; nf < 4; nf++)
#pragma unroll
            for (int r = 0; r < 4; r++) c[mf][nf][r] = 0.f;

    const int NPH = K >> 4;

    auto copy_phase = [&](int ph, int buf) {
        int k0 = ph * 16;
        unsigned abase = smem_base + (unsigned)(buf * 2 * TILE_W) * 4u;
        unsigned bbase = abase + (unsigned)TILE_W * 4u;
#pragma unroll
        for (int r = 0; r < 2; r++) {
            int id  = tid + 256 * r;       // 0..511
            int row = id >> 2;             // 0..127
            int kq  = (id & 3) * 4;        // 0,4,8,12
            const float* ga;
            int oksz = 16;
            if (FUSE_EDGE) {
                ga = &A[(size_t)eid_s[row] * K + k0 + kq];
            } else {
                int valid = (bm + row < M);
                ga = &A[(size_t)(valid ? bm + row : 0) * K + k0 + kq];
                oksz = valid ? 16 : 0;
            }
            cp16(abase + (unsigned)(row * RSTRIDE + kq) * 4u, ga, oksz);
            cp16(bbase + (unsigned)(row * RSTRIDE + kq) * 4u,
                 &Wt[(size_t)row * K + k0 + kq], 16);
        }
    };

    copy_phase(0, 0);
    asm volatile("cp.async.commit_group;\n");

    for (int p = 0; p < NPH; p++) {
        int buf = p & 1;
        if (p + 1 < NPH) {
            copy_phase(p + 1, (p + 1) & 1);
            asm volatile("cp.async.commit_group;\n");
            asm volatile("cp.async.wait_group 1;\n");
        } else {
            asm volatile("cp.async.wait_group 0;\n");
        }
        __syncthreads();

        unsigned aBase = smem_base + (unsigned)(buf * 2 * TILE_W) * 4u
                       + (unsigned)(aRow * RSTRIDE + aK) * 4u;
        unsigned bBase = smem_base + (unsigned)(buf * 2 * TILE_W + TILE_W) * 4u
                       + (unsigned)(bRow * RSTRIDE + bK) * 4u;
#pragma unroll
        for (int ks = 0; ks < 16; ks += 8) {
            unsigned a[4][4], b[4][2];
#pragma unroll
            for (int mf = 0; mf < 4; mf++)
                ldsm_x4(a[mf], aBase + (unsigned)(mf * 16 * RSTRIDE + ks) * 4u);
#pragma unroll
            for (int nf = 0; nf < 4; nf++)
                ldsm_x2(b[nf], bBase + (unsigned)(nf * 8 * RSTRIDE + ks) * 4u);
#pragma unroll
            for (int mf = 0; mf < 4; mf++)
#pragma unroll
                for (int r = 0; r < 4; r++) a[mf][r] = RND(a[mf][r]);
#pragma unroll
            for (int nf = 0; nf < 4; nf++) {
                b[nf][0] = RND(b[nf][0]);
                b[nf][1] = RND(b[nf][1]);
            }
#pragma unroll
            for (int mf = 0; mf < 4; mf++)
#pragma unroll
                for (int nf = 0; nf < 4; nf++)
                    mma_tf32(c[mf][nf], a[mf], b[nf]);
        }
        __syncthreads();
    }

    if (!FUSE_EDGE) {
#pragma unroll
        for (int mf = 0; mf < 4; mf++) {
            int r0 = bm + warp_m + mf * 16 + g;
            int r1 = r0 + 8;
#pragma unroll
            for (int nf = 0; nf < 4; nf++) {
                int col = warp_n + nf * 8 + t * 2;
                float2 bb = *(const float2*)&bias[col];
                if (r0 < M) {
                    float2 v = make_float2(c[mf][nf][0] + bb.x, c[mf][nf][1] + bb.y);
                    *(float2*)&C[(size_t)r0 * HO + col] = v;
                }
                if (r1 < M) {
                    float2 v = make_float2(c[mf][nf][2] + bb.x, c[mf][nf][3] + bb.y);
                    *(float2*)&C[(size_t)r1 * HO + col] = v;
                }
            }
        }
        return;
    }

    // ---- fused phase-2 reduction epilogue ----
    int lr0 = (wid >> 2) * 16 + g;
    int lr1 = lr0 + 8;
    int col_w = tid & 127;        // walker column
    int sel   = tid >> 7;         // 0: ex->g_dn, 1: exm->g_nm

#pragma unroll
    for (int mf = 0; mf < 4; mf++) {
        int r0 = bm + warp_m + mf * 16 + g;
        int r1 = r0 + 8;
        const float* h0 = (r0 < M) ? &g_h[(size_t)g_srcs[r0] * HO] : nullptr;
        const float* h1 = (r1 < M) ? &g_h[(size_t)g_srcs[r1] * HO] : nullptr;
#pragma unroll
        for (int nf = 0; nf < 4; nf++) {
            int col = warp_n + nf * 8 + t * 2;
            float2 bb = *(const float2*)&bias[col];
            float ex0x = 0.f, ex0y = 0.f, em0x = 0.f, em0y = 0.f;
            float ex1x = 0.f, ex1y = 0.f, em1x = 0.f, em1y = 0.f;
            if (r0 < M) {
                float2 hv = *(const float2*)&h0[col];
                float mx = c[mf][nf][0] + bb.x + hv.x;
                float my = c[mf][nf][1] + bb.y + hv.y;
                ex0x = __expf(mx); em0x = ex0x * mx;
                ex0y = __expf(my); em0y = ex0y * my;
            }
            if (r1 < M) {
                float2 hv = *(const float2*)&h1[col];
                float mx = c[mf][nf][2] + bb.x + hv.x;
                float my = c[mf][nf][3] + bb.y + hv.y;
                ex1x = __expf(mx); em1x = ex1x * mx;
                ex1y = __expf(my); em1y = ex1y * my;
            }
            stg_ex [col][lr0] = ex0x;  stg_ex [col + 1][lr0] = ex0y;
            stg_exm[col][lr0] = em0x;  stg_exm[col + 1][lr0] = em0y;
            stg_ex [col][lr1] = ex1x;  stg_ex [col + 1][lr1] = ex1y;
            stg_exm[col][lr1] = em1x;  stg_exm[col + 1][lr1] = em1y;
        }
        __syncthreads();

        const float (*arr)[33] = sel ? stg_exm : stg_ex;
        float* target = sel ? g_nm : g_dn;
#pragma unroll
        for (int run = 0; run < 32; run += 16) {
            int base128 = (run >> 4) * 64 + mf * 16;   // row128 of lr=run
            int cur = node_s[base128];
            float acc = 0.f;
#pragma unroll
            for (int k = 0; k < 16; k++) {
                int nd = node_s[base128 + k];
                float v = arr[col_w][run + k];
                if (nd != cur) {
                    if (cur >= 0) atomicAdd(&target[(size_t)cur * HO + col_w], acc);
                    acc = 0.f;
                    cur = nd;
                }
                acc += v;
            }
            if (cur >= 0) atomicAdd(&target[(size_t)cur * HO + col_w], acc);
        }
        __syncthreads();
    }
}

// ---------------- phase 1: single-pass fused GATv2 attention (float4/lane) --------
__global__ void node_attn_kernel(const float* __restrict__ attn_v) {
    int gid = blockIdx.x * blockDim.x + threadIdx.x;
    int node = gid >> 5;
    int lane = gid & 31;
    if (node >= NN) return;
    int beg = g_off[node], end = g_off[node + 1];

    const float4* featv = (const float4*)g_feat;   // row stride HO/4 = 32
    float4 fd = featv[node * 32 + lane];
    float4 av = __ldg(&((const float4*)attn_v)[lane]);

    float den = 0.f;
    float4 acc = make_float4(0.f, 0.f, 0.f, 0.f);
    for (int i = beg; i < end; i++) {
        int s = g_srcs[i];
        float4 f = featv[s * 32 + lane];
        float vx = f.x + fd.x; vx = vx > 0.f ? vx : 0.2f * vx;
        float vy = f.y + fd.y; vy = vy > 0.f ? vy : 0.2f * vy;
        float vz = f.z + fd.z; vz = vz > 0.f ? vz : 0.2f * vz;
        float vw = f.w + fd.w; vw = vw > 0.f ? vw : 0.2f * vw;
        float sc = vx * av.x + vy * av.y + vz * av.z + vw * av.w;
        sc += __shfl_xor_sync(0xffffffffu, sc, 1);
        sc += __shfl_xor_sync(0xffffffffu, sc, 2);
        sc += __shfl_xor_sync(0xffffffffu, sc, 4);
        float ex = __expf(sc);
        den += ex;
        acc.x += ex * f.x; acc.y += ex * f.y;
        acc.z += ex * f.z; acc.w += ex * f.w;
    }
    float inv = den > 0.f ? 1.f / den : 0.f;
    float4 r = ((const float4*)g_res)[node * 32 + lane];
    float4 o;
    o.x = fmaxf(acc.x * inv + r.x, 0.f);
    o.y = fmaxf(acc.y * inv + r.y, 0.f);
    o.z = fmaxf(acc.z * inv + r.z, 0.f);
    o.w = fmaxf(acc.w * inv + r.w, 0.f);
    ((float4*)g_h)[node * 32 + lane] = o;
}

// ---------------- final: out = nm/dn (float4); reset accumulators + counters ------
__global__ void final_kernel(float* __restrict__ out) {
    int i = blockIdx.x * blockDim.x + threadIdx.x;
    if (i < NN * HO / 4) {
        float4 dn = ((const float4*)g_dn)[i];
        float4 nm = ((const float4*)g_nm)[i];
        float4 o;
        o.x = dn.x > 0.f ? nm.x / dn.x : 0.f;
        o.y = dn.y > 0.f ? nm.y / dn.y : 0.f;
        o.z = dn.z > 0.f ? nm.z / dn.z : 0.f;
        o.w = dn.w > 0.f ? nm.w / dn.w : 0.f;
        ((float4*)out)[i] = o;
        float4 z = make_float4(0.f, 0.f, 0.f, 0.f);
        ((float4*)g_dn)[i] = z;
        ((float4*)g_nm)[i] = z;
    }
    if (i < NN) { g_deg[i] = 0; g_cur[i] = 0; }
}

// ---------------- streams/events: hardened ctor, graceful serial fallback ---------
static cudaStream_t g_s2 = nullptr;
static cudaEvent_t  g_evF = nullptr, g_evJ = nullptr;
static struct StreamInit {
    StreamInit() {
        cudaStream_t s = nullptr;
        cudaEvent_t  e1 = nullptr, e2 = nullptr;
        if (cudaStreamCreateWithFlags(&s, cudaStreamNonBlocking) != cudaSuccess) return;
        if (cudaEventCreateWithFlags(&e1, cudaEventDisableTiming) != cudaSuccess) return;
        if (cudaEventCreateWithFlags(&e2, cudaEventDisableTiming) != cudaSuccess) return;
        g_s2 = s; g_evF = e1; g_evJ = e2;
    }
} g_si;

// ---------------- launch ----------------
extern "C" void kernel_launch(void* const* d_in, const int* in_sizes, int n_in,
                              void* d_out, int out_size) {
    const float* node_feats = (const float*)d_in[0];
    const float* edge_feats = (const float*)d_in[1];
    const int*   src        = (const int*)  d_in[2];
    const int*   dst        = (const int*)  d_in[3];
    const float* W          = (const float*)d_in[4];
    const float* b          = (const float*)d_in[5];
    const float* attn_v     = (const float*)d_in[6];
    const float* Wres       = (const float*)d_in[7];
    const float* bres       = (const float*)d_in[8];
    const float* We         = (const float*)d_in[9];
    const float* be         = (const float*)d_in[10];
    float* out = (float*)d_out;

    void *p_feat, *p_res;
    cudaGetSymbolAddress(&p_feat, g_feat);
    cudaGetSymbolAddress(&p_res,  g_res);

    const int NB_NODE = (NN + 127) / 128;       // 391
    const int NB_EDGE = (EE + 127) / 128;       // 4688
    const int SCAN_BLOCKS = (NN + 255) / 256;   // 196

    bool dual = (g_s2 != nullptr);
    cudaStream_t sC = dual ? g_s2 : (cudaStream_t)0;  // CSR chain stream

    if (dual) {
        // fork: CSR chain runs concurrently with the node GEMM pair
        cudaEventRecord(g_evF, 0);
        cudaStreamWaitEvent(sC, g_evF, 0);
    }

    count_kernel<<<(EE + 255) / 256, 256, 0, sC>>>(dst);
    scan1_kernel<<<SCAN_BLOCKS, 256, 0, sC>>>();
    scan2_kernel<<<1, 256, 0, sC>>>(SCAN_BLOCKS);
    scan3_kernel<<<SCAN_BLOCKS, 256, 0, sC>>>();
    scatter_kernel<<<(EE + 255) / 256, 256, 0, sC>>>(dst, src);

    mma_gemm<0><<<dim3(NB_NODE, 2), 256>>>(node_feats, W, b, (float*)p_feat,
                                           Wres, bres, (float*)p_res, NN, IN_F);

    if (dual) {
        // join: node_attn needs g_feat/g_res (stream 0) AND the CSR (sC)
        cudaEventRecord(g_evJ, sC);
        cudaStreamWaitEvent(0, g_evJ, 0);
    }

    node_attn_kernel<<<(NN * 32 + 255) / 256, 256>>>(attn_v);
    mma_gemm<1><<<NB_EDGE, 256>>>(edge_feats, We, be, nullptr,
                                  nullptr, nullptr, nullptr, EE, EF_F);
    final_kernel<<<(NN * HO / 4 + 255) / 256, 256>>>(out);
}